// round 11
// baseline (speedup 1.0000x reference)
#include <cuda_runtime.h>
#include <cuda_fp16.h>
#include <cuda_bf16.h>
#include <math.h>

#define D_MODEL 1024
#define N_TOK   4096
#define N_HEADS 16
#define HD      64
#define D_FF    4096
#define SEQ     2048

// ---------------- scratch (device globals; no allocation allowed) ----------
__device__ __half g_qh[N_TOK * D_MODEL];
__device__ __half g_kh[N_TOK * D_MODEL];
__device__ __half g_vh[N_TOK * D_MODEL];
__device__ float  g_x1[N_TOK * D_MODEL];
__device__ __nv_bfloat16 g_xnb[N_TOK * D_MODEL];
__device__ __nv_bfloat16 g_atb[N_TOK * D_MODEL];
__device__ __nv_bfloat16 g_hb [N_TOK * D_FF];
__device__ __nv_bfloat16 g_wq[D_MODEL * D_MODEL];
__device__ __nv_bfloat16 g_wk[D_MODEL * D_MODEL];
__device__ __nv_bfloat16 g_wv[D_MODEL * D_MODEL];
__device__ __nv_bfloat16 g_wo[D_MODEL * D_MODEL];
__device__ __nv_bfloat16 g_wg[D_MODEL * D_FF];
__device__ __nv_bfloat16 g_wh[D_MODEL * D_FF];
__device__ __nv_bfloat16 g_wd[D_FF * D_MODEL];
__device__ int g_cnt[N_TOK / 64];      // O-proj row-block completion counters

// ---------------- helpers ---------------------------------------------------
__device__ __forceinline__ unsigned smem_u32(const void* p) {
    unsigned a;
    asm("{ .reg .u64 t; cvta.to.shared.u64 t, %1; cvt.u32.u64 %0, t; }"
        : "=r"(a) : "l"(p));
    return a;
}
__device__ __forceinline__ float ex2f(float x) {
    float y;
    asm("ex2.approx.ftz.f32 %0, %1;" : "=f"(y) : "f"(x));
    return y;
}
__device__ __forceinline__ unsigned packh2(float lo, float hi) {
    unsigned d;
    asm("cvt.rn.f16x2.f32 %0, %1, %2;" : "=r"(d) : "f"(hi), "f"(lo));
    return d;
}
__device__ __forceinline__ void ldsm_x4(unsigned& r0, unsigned& r1,
                                        unsigned& r2, unsigned& r3, unsigned addr) {
    asm volatile("ldmatrix.sync.aligned.m8n8.x4.shared.b16 {%0,%1,%2,%3}, [%4];"
                 : "=r"(r0), "=r"(r1), "=r"(r2), "=r"(r3) : "r"(addr));
}
__device__ __forceinline__ void ldsm_x4_t(unsigned& r0, unsigned& r1,
                                          unsigned& r2, unsigned& r3, unsigned addr) {
    asm volatile("ldmatrix.sync.aligned.m8n8.x4.trans.shared.b16 {%0,%1,%2,%3}, [%4];"
                 : "=r"(r0), "=r"(r1), "=r"(r2), "=r"(r3) : "r"(addr));
}
__device__ __forceinline__ void mma_f16(float* d, unsigned a0, unsigned a1,
                                        unsigned a2, unsigned a3,
                                        unsigned b0, unsigned b1) {
    asm volatile(
        "mma.sync.aligned.m16n8k16.row.col.f32.f16.f16.f32 "
        "{%0,%1,%2,%3}, {%4,%5,%6,%7}, {%8,%9}, {%0,%1,%2,%3};"
        : "+f"(d[0]), "+f"(d[1]), "+f"(d[2]), "+f"(d[3])
        : "r"(a0), "r"(a1), "r"(a2), "r"(a3), "r"(b0), "r"(b1));
}
__device__ __forceinline__ void mma_bf16(float* d, unsigned a0, unsigned a1,
                                         unsigned a2, unsigned a3,
                                         unsigned b0, unsigned b1) {
    asm volatile(
        "mma.sync.aligned.m16n8k16.row.col.f32.bf16.bf16.f32 "
        "{%0,%1,%2,%3}, {%4,%5,%6,%7}, {%8,%9}, {%0,%1,%2,%3};"
        : "+f"(d[0]), "+f"(d[1]), "+f"(d[2]), "+f"(d[3])
        : "r"(a0), "r"(a1), "r"(a2), "r"(a3), "r"(b0), "r"(b1));
}
__device__ __forceinline__ void cp16(unsigned dst, const void* src) {
    asm volatile("cp.async.cg.shared.global [%0], [%1], 16;"
                 :: "r"(dst), "l"(src));
}
#define CP_COMMIT() asm volatile("cp.async.commit_group;")
#define CP_WAIT0()  asm volatile("cp.async.wait_group 0;")

// ---------------- prep kernel: QKV/O weight cvt + rmsnorm1 + cnt reset -----
__global__ void __launch_bounds__(256) prep_kernel(
    const float* __restrict__ x, const float* __restrict__ a_nw,
    __nv_bfloat16* __restrict__ xnb,
    const float* __restrict__ Wq, const float* __restrict__ Wk,
    const float* __restrict__ Wv, const float* __restrict__ Wo,
    __nv_bfloat16* oq, __nv_bfloat16* ok, __nv_bfloat16* ov, __nv_bfloat16* oo)
{
    const int bx = blockIdx.x;
    const int t  = threadIdx.x;
    __shared__ float red[8];

    if (bx < 4096) {
        const int z = bx >> 10;
        const float* s = (z == 0) ? Wq : (z == 1) ? Wk : (z == 2) ? Wv : Wo;
        __nv_bfloat16* d = (z == 0) ? oq : (z == 1) ? ok : (z == 2) ? ov : oo;
        size_t i = (size_t)(bx & 1023) * 256 + t;
        float4 v = ((const float4*)s)[i];
        __nv_bfloat162* dp = (__nv_bfloat162*)d + i * 2;
        dp[0] = __floats2bfloat162_rn(v.x, v.y);
        dp[1] = __floats2bfloat162_rn(v.z, v.w);
        return;
    }

    const int row = bx - 4096;
    if (row == 0 && t < N_TOK / 64) g_cnt[t] = 0;   // reset O-proj counters

    const float4* xr = (const float4*)(x + (size_t)row * D_MODEL);
    float4 v = xr[t];
    float ss = v.x * v.x + v.y * v.y + v.z * v.z + v.w * v.w;
    #pragma unroll
    for (int m = 16; m; m >>= 1) ss += __shfl_xor_sync(0xffffffffu, ss, m);
    if ((t & 31) == 0) red[t >> 5] = ss;
    __syncthreads();
    float tot = 0.f;
    #pragma unroll
    for (int i = 0; i < 8; i++) tot += red[i];
    float r = rsqrtf(tot * (1.0f / D_MODEL) + 1e-6f);
    float4 wv = ((const float4*)a_nw)[t];
    __nv_bfloat162* yr = (__nv_bfloat162*)(xnb + (size_t)row * D_MODEL) + t * 2;
    yr[0] = __floats2bfloat162_rn(v.x * wv.x * r, v.y * wv.y * r);
    yr[1] = __floats2bfloat162_rn(v.z * wv.z * r, v.w * wv.w * r);
}

// ---------------- bf16 HMMA GEMM core, templated M (MF*32 rows) ------------
#define BKh 32
#define SAh 40
#define SBh 136
#define BSTG (BKh * SBh)
#define ASTG4 (128 * SAh)
#define STG4_B ((ASTG4 + BSTG) * 2)
#define G5_SMEM_M128 ((ASTG4 + BSTG) * 2 * 5)           // 94720
#define G5_SMEM_M64  (((64 * SAh) + BSTG) * 2 * 5)      // 69120
#define SWI_STASH (256 * 33 * 4)
#define SWI_SMEM (4 * STG4_B + SWI_STASH)               // 109568

template<int NSTG, int MF>
__device__ __forceinline__ void gemm_kloop(
    const __nv_bfloat16* __restrict__ Ab,
    const __nv_bfloat16* __restrict__ Bb,
    int N, int K, unsigned as_u, unsigned bs_u,
    float (&acc)[MF][4][4], int tid, int lane, int wm, int wn)
{
    constexpr int AST = MF * 32 * SAh;
    const int KC = K / BKh;

    #define LOAD_STAGE(S, C)                                                   \
        do {                                                                   \
            _Pragma("unroll")                                                  \
            for (int t_ = 0; t_ < MF * 128; t_ += 256) {                       \
                int seg = tid + t_;                                            \
                int row_ = seg >> 2, colh_ = (seg & 3) * 8;                    \
                cp16(as_u + ((S) * AST + row_ * SAh + colh_) * 2,              \
                     Ab + (size_t)row_ * K + (C) * BKh + colh_);               \
            }                                                                  \
            _Pragma("unroll")                                                  \
            for (int t_ = 0; t_ < 512; t_ += 256) {                            \
                int seg = tid + t_;                                            \
                int row_ = seg >> 4, colh_ = (seg & 15) * 8;                   \
                cp16(bs_u + ((S) * BSTG + row_ * SBh + colh_) * 2,             \
                     Bb + (size_t)((C) * BKh + row_) * N + colh_);             \
            }                                                                  \
        } while (0)

    #pragma unroll
    for (int s = 0; s < NSTG - 1; s++) {
        LOAD_STAGE(s, s);
        CP_COMMIT();
    }

    for (int c = 0; c < KC; c++) {
        asm volatile("cp.async.wait_group %0;" :: "n"(NSTG - 2));
        __syncthreads();

        if (c + NSTG - 1 < KC) {
            const int s = (c + NSTG - 1) % NSTG;
            LOAD_STAGE(s, c + NSTG - 1);
        }
        CP_COMMIT();

        const int s = c % NSTG;
        const unsigned asb = as_u + s * AST * 2;
        const unsigned bsb = bs_u + s * BSTG * 2;
        #pragma unroll
        for (int ks = 0; ks < 2; ks++) {
            const int k0 = ks * 16;
            unsigned a[MF][4];
            #pragma unroll
            for (int mf = 0; mf < MF; mf++) {
                unsigned addr = asb +
                    ((wm + mf * 16 + (lane & 15)) * SAh + k0 + (lane >> 4) * 8) * 2;
                ldsm_x4(a[mf][0], a[mf][1], a[mf][2], a[mf][3], addr);
            }
            unsigned b[2][4];
            #pragma unroll
            for (int nb = 0; nb < 2; nb++) {
                unsigned addr = bsb +
                    ((k0 + (lane & 15)) * SBh + wn + nb * 16 + (lane >> 4) * 8) * 2;
                ldsm_x4_t(b[nb][0], b[nb][1], b[nb][2], b[nb][3], addr);
            }
            #pragma unroll
            for (int mf = 0; mf < MF; mf++)
                #pragma unroll
                for (int nf = 0; nf < 4; nf++)
                    mma_bf16(acc[mf][nf], a[mf][0], a[mf][1], a[mf][2], a[mf][3],
                             b[nf >> 1][(nf & 1) * 2], b[nf >> 1][(nf & 1) * 2 + 1]);
        }
    }
    #undef LOAD_STAGE
}

template<int MF>
__device__ __forceinline__ void gemm_epilogue(
    float (&acc)[MF][4][4], const float* bias, const float* res,
    float* C, int N, int row0, int col0, int lane, int wm, int wn)
{
    #pragma unroll
    for (int mf = 0; mf < MF; mf++) {
        const int r = row0 + wm + mf * 16 + (lane >> 2);
        #pragma unroll
        for (int nf = 0; nf < 4; nf++) {
            const int cc = col0 + wn + nf * 8 + (lane & 3) * 2;
            float2 v0 = make_float2(acc[mf][nf][0], acc[mf][nf][1]);
            float2 v1 = make_float2(acc[mf][nf][2], acc[mf][nf][3]);
            if (bias) {
                float2 bv = *(const float2*)(bias + cc);
                v0.x += bv.x; v0.y += bv.y;
                v1.x += bv.x; v1.y += bv.y;
            }
            if (res) {
                float2 r0 = *(const float2*)(res + (size_t)r * N + cc);
                float2 r1 = *(const float2*)(res + (size_t)(r + 8) * N + cc);
                v0.x += r0.x; v0.y += r0.y;
                v1.x += r1.x; v1.y += r1.y;
            }
            *(float2*)(C + (size_t)r * N + cc) = v0;
            *(float2*)(C + (size_t)(r + 8) * N + cc) = v1;
        }
    }
}

// generic GEMM kernel (bias+res), templated on MF
template<int MF>
__global__ void __launch_bounds__(256, 2) mma_gemm_kernel(
    const __nv_bfloat16* __restrict__ A, const __nv_bfloat16* __restrict__ B,
    const float* __restrict__ bias, const float* __restrict__ res,
    float* __restrict__ C, int M, int N, int K)
{
    extern __shared__ __nv_bfloat16 smh[];
    const unsigned as_u = smem_u32(smh);
    const int tid = threadIdx.x, lane = tid & 31, warp = tid >> 5;
    const int wm = (warp >> 2) * (MF * 16), wn = (warp & 3) * 32;
    const int row0 = blockIdx.y * (MF * 32), col0 = blockIdx.x * 128;
    float acc[MF][4][4];
    #pragma unroll
    for (int i = 0; i < MF; i++)
        #pragma unroll
        for (int j = 0; j < 4; j++)
            #pragma unroll
            for (int r = 0; r < 4; r++) acc[i][j][r] = 0.f;
    gemm_kloop<5, MF>(A + (size_t)row0 * K, B + col0, N, K,
                      as_u, as_u + 5 * (MF * 32 * SAh) * 2, acc, tid, lane, wm, wn);
    gemm_epilogue<MF>(acc, bias, res, C, N, row0, col0, lane, wm, wn);
}

// O-proj (M=64 tiles) with FUSED second rmsnorm: last CTA per 64-row block
// normalizes those rows (warp-per-row, barrier-free) into xnb.
__global__ void __launch_bounds__(256, 2) mma_gemm_oproj(
    const __nv_bfloat16* __restrict__ A, const __nv_bfloat16* __restrict__ B,
    const float* __restrict__ bias, const float* __restrict__ res,
    float* __restrict__ C, int M, int N, int K,
    const float* __restrict__ f_nw, __nv_bfloat16* __restrict__ xnb)
{
    extern __shared__ __nv_bfloat16 smh[];
    const unsigned as_u = smem_u32(smh);
    const int tid = threadIdx.x, lane = tid & 31, warp = tid >> 5;
    const int wm = (warp >> 2) * 32, wn = (warp & 3) * 32;
    const int row0 = blockIdx.y * 64, col0 = blockIdx.x * 128;
    float acc[2][4][4];
    #pragma unroll
    for (int i = 0; i < 2; i++)
        #pragma unroll
        for (int j = 0; j < 4; j++)
            #pragma unroll
            for (int r = 0; r < 4; r++) acc[i][j][r] = 0.f;
    gemm_kloop<5, 2>(A + (size_t)row0 * K, B + col0, N, K,
                     as_u, as_u + 5 * (64 * SAh) * 2, acc, tid, lane, wm, wn);
    gemm_epilogue<2>(acc, bias, res, C, N, row0, col0, lane, wm, wn);

    // --- fused rmsnorm over this 64-row block, done by the last CTA -------
    __threadfence();
    __shared__ int last;
    if (tid == 0)
        last = (atomicAdd(&g_cnt[blockIdx.y], 1) == (D_MODEL / 128) - 1);
    __syncthreads();
    if (!last) return;
    __threadfence();

    // warp w handles rows row0 + w, w+8, ..., w+56 (1024 floats = 8 f4/lane)
    for (int rr = warp; rr < 64; rr += 8) {
        const int row = row0 + rr;
        const float4* xr = (const float4*)(C + (size_t)row * D_MODEL);
        float4 vv[8];
        float ss = 0.f;
        #pragma unroll
        for (int i = 0; i < 8; i++) {
            vv[i] = xr[lane + i * 32];
            ss += vv[i].x * vv[i].x + vv[i].y * vv[i].y
                + vv[i].z * vv[i].z + vv[i].w * vv[i].w;
        }
        #pragma unroll
        for (int m = 16; m; m >>= 1) ss += __shfl_xor_sync(0xffffffffu, ss, m);
        const float r = rsqrtf(ss * (1.0f / D_MODEL) + 1e-6f);
        __nv_bfloat162* yr = (__nv_bfloat162*)(xnb + (size_t)row * D_MODEL);
        #pragma unroll
        for (int i = 0; i < 8; i++) {
            float4 wv = ((const float4*)f_nw)[lane + i * 32];
            yr[(lane + i * 32) * 2] =
                __floats2bfloat162_rn(vv[i].x * wv.x * r, vv[i].y * wv.y * r);
            yr[(lane + i * 32) * 2 + 1] =
                __floats2bfloat162_rn(vv[i].z * wv.z * r, vv[i].w * wv.w * r);
        }
    }
}

// QKV projections (z<3) + FFN weight conversion plane (z==3).
#define CVT_F4    (3 * 1024 * 1024)
#define CVT_PER   (CVT_F4 / 256)

__global__ void __launch_bounds__(256, 2) mma_gemm_qkv(
    const __nv_bfloat16* __restrict__ A,
    const __nv_bfloat16* __restrict__ B0, const __nv_bfloat16* __restrict__ B1,
    const __nv_bfloat16* __restrict__ B2,
    __half* __restrict__ C0, __half* __restrict__ C1, __half* __restrict__ C2,
    int M, int N, int K,
    const float* __restrict__ Wg, const float* __restrict__ Whid,
    const float* __restrict__ Wd,
    __nv_bfloat16* __restrict__ og, __nv_bfloat16* __restrict__ oh,
    __nv_bfloat16* __restrict__ od)
{
    if (blockIdx.z == 3) {
        const int j = blockIdx.y * 8 + blockIdx.x;   // 0..255
        #pragma unroll 4
        for (int t = 0; t < CVT_PER; t += 256) {
            int idx = j * CVT_PER + t + (int)threadIdx.x;
            int m   = idx >> 20;
            int loc = idx & 0xFFFFF;
            const float* s = (m == 0) ? Wg : (m == 1) ? Whid : Wd;
            __nv_bfloat16* d = (m == 0) ? og : (m == 1) ? oh : od;
            float4 v = ((const float4*)s)[loc];
            __nv_bfloat162* dp = (__nv_bfloat162*)d + (size_t)loc * 2;
            dp[0] = __floats2bfloat162_rn(v.x, v.y);
            dp[1] = __floats2bfloat162_rn(v.z, v.w);
        }
        return;
    }

    extern __shared__ __nv_bfloat16 smh[];
    const unsigned as_u = smem_u32(smh);
    const __nv_bfloat16* B = (blockIdx.z == 0) ? B0 : (blockIdx.z == 1) ? B1 : B2;
    __half*              C = (blockIdx.z == 0) ? C0 : (blockIdx.z == 1) ? C1 : C2;
    const float sc = (blockIdx.z == 0) ? 0.125f * 1.4426950408889634f : 1.0f;
    const int tid = threadIdx.x, lane = tid & 31, warp = tid >> 5;
    const int wm = (warp >> 2) * 64, wn = (warp & 3) * 32;
    const int row0 = blockIdx.y * 128, col0 = blockIdx.x * 128;
    float acc[4][4][4];
    #pragma unroll
    for (int i = 0; i < 4; i++)
        #pragma unroll
        for (int j = 0; j < 4; j++)
            #pragma unroll
            for (int r = 0; r < 4; r++) acc[i][j][r] = 0.f;
    gemm_kloop<5, 4>(A + (size_t)row0 * K, B + col0, N, K,
                     as_u, as_u + 5 * ASTG4 * 2, acc, tid, lane, wm, wn);
    #pragma unroll
    for (int mf = 0; mf < 4; mf++) {
        const int r = row0 + wm + mf * 16 + (lane >> 2);
        #pragma unroll
        for (int nf = 0; nf < 4; nf++) {
            const int cc = col0 + wn + nf * 8 + (lane & 3) * 2;
            *(__half2*)(C + (size_t)r * N + cc) =
                __floats2half2_rn(acc[mf][nf][0] * sc, acc[mf][nf][1] * sc);
            *(__half2*)(C + (size_t)(r + 8) * N + cc) =
                __floats2half2_rn(acc[mf][nf][2] * sc, acc[mf][nf][3] * sc);
        }
    }
}

// ---------------- fused SwiGLU GEMM: hb = bf16(silu(A@Wg) * (A@Wh)) --------
__global__ void __launch_bounds__(256, 2) swiglu_gemm_kernel(
    const __nv_bfloat16* __restrict__ A,
    const __nv_bfloat16* __restrict__ Wg, const __nv_bfloat16* __restrict__ Wh,
    __nv_bfloat16* __restrict__ hb, int M, int N, int K)
{
    extern __shared__ __nv_bfloat16 smh[];
    const unsigned as_u = smem_u32(smh);
    const unsigned bs_u = as_u + 4 * ASTG4 * 2;
    unsigned* stash = (unsigned*)((char*)smh + 4 * STG4_B);

    const int tid = threadIdx.x, lane = tid & 31, warp = tid >> 5;
    const int wm = (warp >> 2) * 64, wn = (warp & 3) * 32;
    const int row0 = blockIdx.y * 128, col0 = blockIdx.x * 128;

    float acc[4][4][4];
    #pragma unroll
    for (int i = 0; i < 4; i++)
        #pragma unroll
        for (int j = 0; j < 4; j++)
            #pragma unroll
            for (int r = 0; r < 4; r++) acc[i][j][r] = 0.f;

    gemm_kloop<4, 4>(A + (size_t)row0 * K, Wg + col0, N, K,
                     as_u, bs_u, acc, tid, lane, wm, wn);

    unsigned* st = stash + tid * 33;
    #pragma unroll
    for (int mf = 0; mf < 4; mf++)
        #pragma unroll
        for (int nf = 0; nf < 4; nf++) {
            float s0 = acc[mf][nf][0]; s0 = s0 / (1.f + __expf(-s0));
            float s1 = acc[mf][nf][1]; s1 = s1 / (1.f + __expf(-s1));
            float s2 = acc[mf][nf][2]; s2 = s2 / (1.f + __expf(-s2));
            float s3 = acc[mf][nf][3]; s3 = s3 / (1.f + __expf(-s3));
            __nv_bfloat162 p0 = __floats2bfloat162_rn(s0, s1);
            __nv_bfloat162 p1 = __floats2bfloat162_rn(s2, s3);
            st[mf * 8 + nf * 2]     = *(unsigned*)&p0;
            st[mf * 8 + nf * 2 + 1] = *(unsigned*)&p1;
        }

    __syncthreads();

    #pragma unroll
    for (int i = 0; i < 4; i++)
        #pragma unroll
        for (int j = 0; j < 4; j++)
            #pragma unroll
            for (int r = 0; r < 4; r++) acc[i][j][r] = 0.f;

    gemm_kloop<4, 4>(A + (size_t)row0 * K, Wh + col0, N, K,
                     as_u, bs_u, acc, tid, lane, wm, wn);

    #pragma unroll
    for (int mf = 0; mf < 4; mf++) {
        const int r = row0 + wm + mf * 16 + (lane >> 2);
        #pragma unroll
        for (int nf = 0; nf < 4; nf++) {
            const int cc = col0 + wn + nf * 8 + (lane & 3) * 2;
            unsigned p0 = st[mf * 8 + nf * 2];
            unsigned p1 = st[mf * 8 + nf * 2 + 1];
            float g0 = __uint_as_float(p0 << 16);
            float g1 = __uint_as_float(p0 & 0xffff0000u);
            float g2 = __uint_as_float(p1 << 16);
            float g3 = __uint_as_float(p1 & 0xffff0000u);
            *(__nv_bfloat162*)(hb + (size_t)r * N + cc) =
                __floats2bfloat162_rn(g0 * acc[mf][nf][0], g1 * acc[mf][nf][1]);
            *(__nv_bfloat162*)(hb + (size_t)(r + 8) * N + cc) =
                __floats2bfloat162_rn(g2 * acc[mf][nf][2], g3 * acc[mf][nf][3]);
        }
    }
}

// ---------------- flash attention (f16 tensor path) ------------------------
#define QH 72
#define FQ_B (128 * QH * 2)
#define FK_B (64 * QH * 2)
#define FL_SMEM (FQ_B + 4 * FK_B)

__global__ void __launch_bounds__(256, 2) flash4_kernel(
    const __half* __restrict__ Qh, const __half* __restrict__ Kh,
    const __half* __restrict__ Vh, __nv_bfloat16* __restrict__ O)
{
    extern __shared__ char fsm[];
    const unsigned qs_u = smem_u32(fsm);
    const unsigned kb_u = qs_u + FQ_B;
    const unsigned vb_u = qs_u + FQ_B + 2 * FK_B;

    const int tid  = threadIdx.x;
    const int lane = tid & 31;
    const int warp = tid >> 5;
    const int bq = blockIdx.x, head = blockIdx.y, b = blockIdx.z;
    const size_t qtok0 = (size_t)b * SEQ + (size_t)bq * 128;
    const size_t ktokb = (size_t)b * SEQ;
    const int col0 = head * HD;
    const int m0 = warp * 16;

    #pragma unroll
    for (int j = 0; j < 4; j++) {
        int id = tid + j * 256;
        int r = id >> 3, c = (id & 7) * 8;
        cp16(qs_u + (r * QH + c) * 2, Qh + (qtok0 + r) * D_MODEL + col0 + c);
    }
    #pragma unroll
    for (int j = 0; j < 2; j++) {
        int id = tid + j * 256;
        int r = id >> 3, c = (id & 7) * 8;
        cp16(kb_u + (r * QH + c) * 2, Kh + (ktokb + r) * D_MODEL + col0 + c);
        cp16(vb_u + (r * QH + c) * 2, Vh + (ktokb + r) * D_MODEL + col0 + c);
    }
    CP_COMMIT();
    CP_WAIT0();
    __syncthreads();

    float m0s = -INFINITY, m1s = -INFINITY, l0s = 0.f, l1s = 0.f;
    float oacc[8][4];
    #pragma unroll
    for (int i = 0; i < 8; i++)
        #pragma unroll
        for (int j = 0; j < 4; j++) oacc[i][j] = 0.f;

    for (int kvt = 0; kvt < SEQ / 64; kvt++) {
        const int buf = kvt & 1;
        const bool pre = (kvt + 1) < SEQ / 64;
        if (pre) {
            const size_t kt = ktokb + (size_t)(kvt + 1) * 64;
            const unsigned kbd = kb_u + (buf ^ 1) * FK_B;
            const unsigned vbd = vb_u + (buf ^ 1) * FK_B;
            #pragma unroll
            for (int j = 0; j < 2; j++) {
                int id = tid + j * 256;
                int r = id >> 3, c = (id & 7) * 8;
                cp16(kbd + (r * QH + c) * 2, Kh + (kt + r) * D_MODEL + col0 + c);
                cp16(vbd + (r * QH + c) * 2, Vh + (kt + r) * D_MODEL + col0 + c);
            }
        }
        CP_COMMIT();

        float sacc[8][4];
        #pragma unroll
        for (int i = 0; i < 8; i++)
            #pragma unroll
            for (int j = 0; j < 4; j++) sacc[i][j] = 0.f;

        const unsigned kfb = kb_u + buf * FK_B;
        #pragma unroll
        for (int ks = 0; ks < 4; ks++) {
            const int k0 = ks * 16;
            unsigned a0, a1, a2, a3;
            ldsm_x4(a0, a1, a2, a3,
                    qs_u + ((m0 + (lane & 15)) * QH + k0 + (lane >> 4) * 8) * 2);
            #pragma unroll
            for (int ng = 0; ng < 4; ng++) {
                unsigned b0, b1, b2, b3;
                ldsm_x4(b0, b1, b2, b3,
                        kfb + ((ng * 16 + (lane & 15)) * QH + k0 + (lane >> 4) * 8) * 2);
                mma_f16(sacc[ng * 2],     a0, a1, a2, a3, b0, b2);
                mma_f16(sacc[ng * 2 + 1], a0, a1, a2, a3, b1, b3);
            }
        }

        float mx0 = -INFINITY, mx1 = -INFINITY;
        #pragma unroll
        for (int nf = 0; nf < 8; nf++) {
            mx0 = fmaxf(mx0, fmaxf(sacc[nf][0], sacc[nf][1]));
            mx1 = fmaxf(mx1, fmaxf(sacc[nf][2], sacc[nf][3]));
        }
        mx0 = fmaxf(mx0, __shfl_xor_sync(0xffffffffu, mx0, 1));
        mx0 = fmaxf(mx0, __shfl_xor_sync(0xffffffffu, mx0, 2));
        mx1 = fmaxf(mx1, __shfl_xor_sync(0xffffffffu, mx1, 1));
        mx1 = fmaxf(mx1, __shfl_xor_sync(0xffffffffu, mx1, 2));

        const float mn0 = fmaxf(m0s, mx0);
        const float mn1 = fmaxf(m1s, mx1);
        const float al0 = ex2f(m0s - mn0);
        const float al1 = ex2f(m1s - mn1);

        unsigned pa0[8], pa1[8];
        float ls0 = 0.f, ls1 = 0.f;
        #pragma unroll
        for (int nf = 0; nf < 8; nf++) {
            float p0 = ex2f(sacc[nf][0] - mn0);
            float p1 = ex2f(sacc[nf][1] - mn0);
            float p2 = ex2f(sacc[nf][2] - mn1);
            float p3 = ex2f(sacc[nf][3] - mn1);
            ls0 += p0 + p1;
            ls1 += p2 + p3;
            pa0[nf] = packh2(p0, p1);
            pa1[nf] = packh2(p2, p3);
        }
        ls0 += __shfl_xor_sync(0xffffffffu, ls0, 1);
        ls0 += __shfl_xor_sync(0xffffffffu, ls0, 2);
        ls1 += __shfl_xor_sync(0xffffffffu, ls1, 1);
        ls1 += __shfl_xor_sync(0xffffffffu, ls1, 2);
        l0s = l0s * al0 + ls0;
        l1s = l1s * al1 + ls1;
        m0s = mn0; m1s = mn1;

        #pragma unroll
        for (int nf = 0; nf < 8; nf++) {
            oacc[nf][0] *= al0; oacc[nf][1] *= al0;
            oacc[nf][2] *= al1; oacc[nf][3] *= al1;
        }

        const unsigned vhb = vb_u + buf * FK_B;
        #pragma unroll
        for (int ks = 0; ks < 4; ks++) {
            unsigned a0 = pa0[2 * ks],     a1 = pa1[2 * ks];
            unsigned a2 = pa0[2 * ks + 1], a3 = pa1[2 * ks + 1];
            #pragma unroll
            for (int no = 0; no < 4; no++) {
                unsigned addr = vhb +
                    ((ks * 16 + (lane & 15)) * QH + no * 16 + (lane >> 4) * 8) * 2;
                unsigned b0, b1, b2, b3;
                ldsm_x4_t(b0, b1, b2, b3, addr);
                mma_f16(oacc[no * 2],     a0, a1, a2, a3, b0, b1);
                mma_f16(oacc[no * 2 + 1], a0, a1, a2, a3, b2, b3);
            }
        }

        CP_WAIT0();
        __syncthreads();
    }

    const float i0 = 1.f / l0s;
    const float i1 = 1.f / l1s;
    const size_t row0 = qtok0 + m0 + (lane >> 2);
    #pragma unroll
    for (int no = 0; no < 8; no++) {
        const int cw = col0 + no * 8 + (lane & 3) * 2;
        *(__nv_bfloat162*)(O + row0 * D_MODEL + cw) =
            __floats2bfloat162_rn(oacc[no][0] * i0, oacc[no][1] * i0);
        *(__nv_bfloat162*)(O + (row0 + 8) * D_MODEL + cw) =
            __floats2bfloat162_rn(oacc[no][2] * i1, oacc[no][3] * i1);
    }
}

// ---------------- driver ----------------------------------------------------
extern "C" void kernel_launch(void* const* d_in, const int* in_sizes, int n_in,
                              void* d_out, int out_size)
{
    const float* x       = (const float*)d_in[0];
    const float* W_q     = (const float*)d_in[1];
    const float* W_k     = (const float*)d_in[2];
    const float* W_v     = (const float*)d_in[3];
    const float* W_o     = (const float*)d_in[4];
    const float* b_o     = (const float*)d_in[5];
    const float* a_nw    = (const float*)d_in[6];
    const float* f_nw    = (const float*)d_in[7];
    const float* W_gate  = (const float*)d_in[8];
    const float* W_hid   = (const float*)d_in[9];
    const float* W_out   = (const float*)d_in[10];
    const float* b_out   = (const float*)d_in[11];
    float* out = (float*)d_out;

    float *x1;
    __half *qh, *kh, *vh;
    __nv_bfloat16 *xnb, *atb, *hb, *wq, *wk, *wv, *wo, *wg, *wh, *wd;
    cudaGetSymbolAddress((void**)&qh,  g_qh);
    cudaGetSymbolAddress((void**)&kh,  g_kh);
    cudaGetSymbolAddress((void**)&vh,  g_vh);
    cudaGetSymbolAddress((void**)&x1,  g_x1);
    cudaGetSymbolAddress((void**)&xnb, g_xnb);
    cudaGetSymbolAddress((void**)&atb, g_atb);
    cudaGetSymbolAddress((void**)&hb,  g_hb);
    cudaGetSymbolAddress((void**)&wq,  g_wq);
    cudaGetSymbolAddress((void**)&wk,  g_wk);
    cudaGetSymbolAddress((void**)&wv,  g_wv);
    cudaGetSymbolAddress((void**)&wo,  g_wo);
    cudaGetSymbolAddress((void**)&wg,  g_wg);
    cudaGetSymbolAddress((void**)&wh,  g_wh);
    cudaGetSymbolAddress((void**)&wd,  g_wd);

    cudaFuncSetAttribute(flash4_kernel,
                         cudaFuncAttributeMaxDynamicSharedMemorySize, FL_SMEM);
    cudaFuncSetAttribute(mma_gemm_kernel<4>,
                         cudaFuncAttributeMaxDynamicSharedMemorySize, G5_SMEM_M128);
    cudaFuncSetAttribute(mma_gemm_oproj,
                         cudaFuncAttributeMaxDynamicSharedMemorySize, G5_SMEM_M64);
    cudaFuncSetAttribute(mma_gemm_qkv,
                         cudaFuncAttributeMaxDynamicSharedMemorySize, G5_SMEM_M128);
    cudaFuncSetAttribute(swiglu_gemm_kernel,
                         cudaFuncAttributeMaxDynamicSharedMemorySize, SWI_SMEM);

    // 1) QKV/O weight cvt + attn rmsnorm + counter reset, one launch
    prep_kernel<<<8192, 256>>>(x, a_nw, xnb, W_q, W_k, W_v, W_o,
                               wq, wk, wv, wo);

    // 2) q, k, v projections + FFN weight conversion plane (z==3 fills tail)
    dim3 gqkv(D_MODEL / 128, N_TOK / 128, 4);
    mma_gemm_qkv<<<gqkv, 256, G5_SMEM_M128>>>(xnb, wq, wk, wv, qh, kh, vh,
                                              N_TOK, D_MODEL, D_MODEL,
                                              W_gate, W_hid, W_out, wg, wh, wd);

    // 3) attention -> bf16
    dim3 ga(SEQ / 128, N_HEADS, 2);
    flash4_kernel<<<ga, 256, FL_SMEM>>>(qh, kh, vh, atb);

    // 4) output projection + bias + residual + FUSED ffn rmsnorm
    dim3 go(D_MODEL / 128, N_TOK / 64);
    mma_gemm_oproj<<<go, 256, G5_SMEM_M64>>>(atb, wo, b_o, x, x1,
                                             N_TOK, D_MODEL, D_MODEL,
                                             f_nw, xnb);

    // 5+6) fused gate/hidden GEMMs + SwiGLU -> hb bf16
    dim3 gf(D_FF / 128, N_TOK / 128);
    swiglu_gemm_kernel<<<gf, 256, SWI_SMEM>>>(xnb, wg, wh, hb,
                                              N_TOK, D_FF, D_MODEL);

    // 7) down projection + bias + residual -> out
    dim3 gd(D_MODEL / 128, N_TOK / 128);
    mma_gemm_kernel<4><<<gd, 256, G5_SMEM_M128>>>(hb, wd, b_out, x1, out,
                                                  N_TOK, D_MODEL, D_FF);
}

// round 12
// speedup vs baseline: 1.0059x; 1.0059x over previous
#include <cuda_runtime.h>
#include <cuda_fp16.h>
#include <cuda_bf16.h>
#include <math.h>

#define D_MODEL 1024
#define N_TOK   4096
#define N_HEADS 16
#define HD      64
#define D_FF    4096
#define SEQ     2048

// ---------------- scratch (device globals; no allocation allowed) ----------
__device__ __half g_qh[N_TOK * D_MODEL];
__device__ __half g_kh[N_TOK * D_MODEL];
__device__ __half g_vh[N_TOK * D_MODEL];
__device__ float  g_x1[N_TOK * D_MODEL];
__device__ __nv_bfloat16 g_xnb[N_TOK * D_MODEL];
__device__ __nv_bfloat16 g_atb[N_TOK * D_MODEL];
__device__ __nv_bfloat16 g_hb [N_TOK * D_FF];
__device__ __nv_bfloat16 g_wq[D_MODEL * D_MODEL];
__device__ __nv_bfloat16 g_wk[D_MODEL * D_MODEL];
__device__ __nv_bfloat16 g_wv[D_MODEL * D_MODEL];
__device__ __nv_bfloat16 g_wo[D_MODEL * D_MODEL];
__device__ __nv_bfloat16 g_wg[D_MODEL * D_FF];
__device__ __nv_bfloat16 g_wh[D_MODEL * D_FF];
__device__ __nv_bfloat16 g_wd[D_FF * D_MODEL];

// ---------------- helpers ---------------------------------------------------
__device__ __forceinline__ unsigned smem_u32(const void* p) {
    unsigned a;
    asm("{ .reg .u64 t; cvta.to.shared.u64 t, %1; cvt.u32.u64 %0, t; }"
        : "=r"(a) : "l"(p));
    return a;
}
__device__ __forceinline__ float ex2f(float x) {
    float y;
    asm("ex2.approx.ftz.f32 %0, %1;" : "=f"(y) : "f"(x));
    return y;
}
__device__ __forceinline__ unsigned packh2(float lo, float hi) {
    unsigned d;
    asm("cvt.rn.f16x2.f32 %0, %1, %2;" : "=r"(d) : "f"(hi), "f"(lo));
    return d;
}
__device__ __forceinline__ void ldsm_x4(unsigned& r0, unsigned& r1,
                                        unsigned& r2, unsigned& r3, unsigned addr) {
    asm volatile("ldmatrix.sync.aligned.m8n8.x4.shared.b16 {%0,%1,%2,%3}, [%4];"
                 : "=r"(r0), "=r"(r1), "=r"(r2), "=r"(r3) : "r"(addr));
}
__device__ __forceinline__ void ldsm_x4_t(unsigned& r0, unsigned& r1,
                                          unsigned& r2, unsigned& r3, unsigned addr) {
    asm volatile("ldmatrix.sync.aligned.m8n8.x4.trans.shared.b16 {%0,%1,%2,%3}, [%4];"
                 : "=r"(r0), "=r"(r1), "=r"(r2), "=r"(r3) : "r"(addr));
}
__device__ __forceinline__ void mma_f16(float* d, unsigned a0, unsigned a1,
                                        unsigned a2, unsigned a3,
                                        unsigned b0, unsigned b1) {
    asm volatile(
        "mma.sync.aligned.m16n8k16.row.col.f32.f16.f16.f32 "
        "{%0,%1,%2,%3}, {%4,%5,%6,%7}, {%8,%9}, {%0,%1,%2,%3};"
        : "+f"(d[0]), "+f"(d[1]), "+f"(d[2]), "+f"(d[3])
        : "r"(a0), "r"(a1), "r"(a2), "r"(a3), "r"(b0), "r"(b1));
}
__device__ __forceinline__ void mma_bf16(float* d, unsigned a0, unsigned a1,
                                         unsigned a2, unsigned a3,
                                         unsigned b0, unsigned b1) {
    asm volatile(
        "mma.sync.aligned.m16n8k16.row.col.f32.bf16.bf16.f32 "
        "{%0,%1,%2,%3}, {%4,%5,%6,%7}, {%8,%9}, {%0,%1,%2,%3};"
        : "+f"(d[0]), "+f"(d[1]), "+f"(d[2]), "+f"(d[3])
        : "r"(a0), "r"(a1), "r"(a2), "r"(a3), "r"(b0), "r"(b1));
}
__device__ __forceinline__ void cp16(unsigned dst, const void* src) {
    asm volatile("cp.async.cg.shared.global [%0], [%1], 16;"
                 :: "r"(dst), "l"(src));
}
#define CP_COMMIT() asm volatile("cp.async.commit_group;")
#define CP_WAIT0()  asm volatile("cp.async.wait_group 0;")

// ---------------- prep kernel: QKV weight cvt + rmsnorm1 -------------------
// blocks [0,3072): convert wq/wk/wv (1024 blocks each)
// blocks [3072,7168): rmsnorm row (bx - 3072)
__global__ void __launch_bounds__(256) prep_kernel(
    const float* __restrict__ x, const float* __restrict__ a_nw,
    __nv_bfloat16* __restrict__ xnb,
    const float* __restrict__ Wq, const float* __restrict__ Wk,
    const float* __restrict__ Wv,
    __nv_bfloat16* oq, __nv_bfloat16* ok, __nv_bfloat16* ov)
{
    const int bx = blockIdx.x;
    const int t  = threadIdx.x;
    __shared__ float red[8];

    if (bx < 3072) {
        const int z = bx >> 10;
        const float* s = (z == 0) ? Wq : (z == 1) ? Wk : Wv;
        __nv_bfloat16* d = (z == 0) ? oq : (z == 1) ? ok : ov;
        size_t i = (size_t)(bx & 1023) * 256 + t;
        float4 v = ((const float4*)s)[i];
        __nv_bfloat162* dp = (__nv_bfloat162*)d + i * 2;
        dp[0] = __floats2bfloat162_rn(v.x, v.y);
        dp[1] = __floats2bfloat162_rn(v.z, v.w);
        return;
    }

    const int row = bx - 3072;
    const float4* xr = (const float4*)(x + (size_t)row * D_MODEL);
    float4 v = xr[t];
    float ss = v.x * v.x + v.y * v.y + v.z * v.z + v.w * v.w;
    #pragma unroll
    for (int m = 16; m; m >>= 1) ss += __shfl_xor_sync(0xffffffffu, ss, m);
    if ((t & 31) == 0) red[t >> 5] = ss;
    __syncthreads();
    float tot = 0.f;
    #pragma unroll
    for (int i = 0; i < 8; i++) tot += red[i];
    float r = rsqrtf(tot * (1.0f / D_MODEL) + 1e-6f);
    float4 wv = ((const float4*)a_nw)[t];
    __nv_bfloat162* yr = (__nv_bfloat162*)(xnb + (size_t)row * D_MODEL) + t * 2;
    yr[0] = __floats2bfloat162_rn(v.x * wv.x * r, v.y * wv.y * r);
    yr[1] = __floats2bfloat162_rn(v.z * wv.z * r, v.w * wv.w * r);
}

// ---------------- rmsnorm (standalone, second norm) ------------------------
__global__ void __launch_bounds__(256) rmsnorm_kernel(
    const float* __restrict__ x, const float* __restrict__ w,
    __nv_bfloat16* __restrict__ y)
{
    int row = blockIdx.x;
    int t   = threadIdx.x;
    const float4* xr = (const float4*)(x + (size_t)row * D_MODEL);
    float4 v = xr[t];
    float ss = v.x * v.x + v.y * v.y + v.z * v.z + v.w * v.w;
    #pragma unroll
    for (int m = 16; m; m >>= 1) ss += __shfl_xor_sync(0xffffffffu, ss, m);
    __shared__ float red[8];
    if ((t & 31) == 0) red[t >> 5] = ss;
    __syncthreads();
    float tot = 0.f;
    #pragma unroll
    for (int i = 0; i < 8; i++) tot += red[i];
    float r = rsqrtf(tot * (1.0f / D_MODEL) + 1e-6f);
    float4 wv = ((const float4*)w)[t];
    __nv_bfloat162* yr = (__nv_bfloat162*)(y + (size_t)row * D_MODEL) + t * 2;
    yr[0] = __floats2bfloat162_rn(v.x * wv.x * r, v.y * wv.y * r);
    yr[1] = __floats2bfloat162_rn(v.z * wv.z * r, v.w * wv.w * r);
}

// ---------------- bf16 HMMA GEMM core, templated M (MF*32 rows) ------------
#define BKh 32
#define SAh 40
#define SBh 136
#define BSTG (BKh * SBh)
#define ASTG4 (128 * SAh)
#define STG4_B ((ASTG4 + BSTG) * 2)
#define G5_SMEM_M128 ((ASTG4 + BSTG) * 2 * 5)           // 94720
#define G5_SMEM_M64  (((64 * SAh) + BSTG) * 2 * 5)      // 69120
#define SWI_STASH (256 * 33 * 4)
#define SWI_SMEM (4 * STG4_B + SWI_STASH)               // 109568

template<int NSTG, int MF>
__device__ __forceinline__ void gemm_kloop(
    const __nv_bfloat16* __restrict__ Ab,
    const __nv_bfloat16* __restrict__ Bb,
    int N, int K, unsigned as_u, unsigned bs_u,
    float (&acc)[MF][4][4], int tid, int lane, int wm, int wn)
{
    constexpr int AST = MF * 32 * SAh;
    const int KC = K / BKh;

    #define LOAD_STAGE(S, C)                                                   \
        do {                                                                   \
            _Pragma("unroll")                                                  \
            for (int t_ = 0; t_ < MF * 128; t_ += 256) {                       \
                int seg = tid + t_;                                            \
                int row_ = seg >> 2, colh_ = (seg & 3) * 8;                    \
                cp16(as_u + ((S) * AST + row_ * SAh + colh_) * 2,              \
                     Ab + (size_t)row_ * K + (C) * BKh + colh_);               \
            }                                                                  \
            _Pragma("unroll")                                                  \
            for (int t_ = 0; t_ < 512; t_ += 256) {                            \
                int seg = tid + t_;                                            \
                int row_ = seg >> 4, colh_ = (seg & 15) * 8;                   \
                cp16(bs_u + ((S) * BSTG + row_ * SBh + colh_) * 2,             \
                     Bb + (size_t)((C) * BKh + row_) * N + colh_);             \
            }                                                                  \
        } while (0)

    #pragma unroll
    for (int s = 0; s < NSTG - 1; s++) {
        LOAD_STAGE(s, s);
        CP_COMMIT();
    }

    for (int c = 0; c < KC; c++) {
        asm volatile("cp.async.wait_group %0;" :: "n"(NSTG - 2));
        __syncthreads();

        if (c + NSTG - 1 < KC) {
            const int s = (c + NSTG - 1) % NSTG;
            LOAD_STAGE(s, c + NSTG - 1);
        }
        CP_COMMIT();

        const int s = c % NSTG;
        const unsigned asb = as_u + s * AST * 2;
        const unsigned bsb = bs_u + s * BSTG * 2;
        #pragma unroll
        for (int ks = 0; ks < 2; ks++) {
            const int k0 = ks * 16;
            unsigned a[MF][4];
            #pragma unroll
            for (int mf = 0; mf < MF; mf++) {
                unsigned addr = asb +
                    ((wm + mf * 16 + (lane & 15)) * SAh + k0 + (lane >> 4) * 8) * 2;
                ldsm_x4(a[mf][0], a[mf][1], a[mf][2], a[mf][3], addr);
            }
            unsigned b[2][4];
            #pragma unroll
            for (int nb = 0; nb < 2; nb++) {
                unsigned addr = bsb +
                    ((k0 + (lane & 15)) * SBh + wn + nb * 16 + (lane >> 4) * 8) * 2;
                ldsm_x4_t(b[nb][0], b[nb][1], b[nb][2], b[nb][3], addr);
            }
            #pragma unroll
            for (int mf = 0; mf < MF; mf++)
                #pragma unroll
                for (int nf = 0; nf < 4; nf++)
                    mma_bf16(acc[mf][nf], a[mf][0], a[mf][1], a[mf][2], a[mf][3],
                             b[nf >> 1][(nf & 1) * 2], b[nf >> 1][(nf & 1) * 2 + 1]);
        }
    }
    #undef LOAD_STAGE
}

template<int MF>
__device__ __forceinline__ void gemm_epilogue(
    float (&acc)[MF][4][4], const float* bias, const float* res,
    float* C, int N, int row0, int col0, int lane, int wm, int wn)
{
    #pragma unroll
    for (int mf = 0; mf < MF; mf++) {
        const int r = row0 + wm + mf * 16 + (lane >> 2);
        #pragma unroll
        for (int nf = 0; nf < 4; nf++) {
            const int cc = col0 + wn + nf * 8 + (lane & 3) * 2;
            float2 v0 = make_float2(acc[mf][nf][0], acc[mf][nf][1]);
            float2 v1 = make_float2(acc[mf][nf][2], acc[mf][nf][3]);
            if (bias) {
                float2 bv = *(const float2*)(bias + cc);
                v0.x += bv.x; v0.y += bv.y;
                v1.x += bv.x; v1.y += bv.y;
            }
            if (res) {
                float2 r0 = *(const float2*)(res + (size_t)r * N + cc);
                float2 r1 = *(const float2*)(res + (size_t)(r + 8) * N + cc);
                v0.x += r0.x; v0.y += r0.y;
                v1.x += r1.x; v1.y += r1.y;
            }
            *(float2*)(C + (size_t)r * N + cc) = v0;
            *(float2*)(C + (size_t)(r + 8) * N + cc) = v1;
        }
    }
}

// generic GEMM kernel (bias+res), templated on MF
template<int MF>
__global__ void __launch_bounds__(256, 2) mma_gemm_kernel(
    const __nv_bfloat16* __restrict__ A, const __nv_bfloat16* __restrict__ B,
    const float* __restrict__ bias, const float* __restrict__ res,
    float* __restrict__ C, int M, int N, int K)
{
    extern __shared__ __nv_bfloat16 smh[];
    const unsigned as_u = smem_u32(smh);
    const int tid = threadIdx.x, lane = tid & 31, warp = tid >> 5;
    const int wm = (warp >> 2) * (MF * 16), wn = (warp & 3) * 32;
    const int row0 = blockIdx.y * (MF * 32), col0 = blockIdx.x * 128;
    float acc[MF][4][4];
    #pragma unroll
    for (int i = 0; i < MF; i++)
        #pragma unroll
        for (int j = 0; j < 4; j++)
            #pragma unroll
            for (int r = 0; r < 4; r++) acc[i][j][r] = 0.f;
    gemm_kloop<5, MF>(A + (size_t)row0 * K, B + col0, N, K,
                      as_u, as_u + 5 * (MF * 32 * SAh) * 2, acc, tid, lane, wm, wn);
    gemm_epilogue<MF>(acc, bias, res, C, N, row0, col0, lane, wm, wn);
}

// QKV projections (z<3) + weight conversion plane (z==3: wo+wg+wh+wd).
#define CVT_F4   (262144 + 3 * 1048576)   // wo (2^18 f4) + wg/wh/wd (3 x 2^20 f4)
#define CVT_PER  (CVT_F4 / 256)           // 13312 float4 per CTA

__global__ void __launch_bounds__(256, 2) mma_gemm_qkv(
    const __nv_bfloat16* __restrict__ A,
    const __nv_bfloat16* __restrict__ B0, const __nv_bfloat16* __restrict__ B1,
    const __nv_bfloat16* __restrict__ B2,
    __half* __restrict__ C0, __half* __restrict__ C1, __half* __restrict__ C2,
    int M, int N, int K,
    const float* __restrict__ Wo, const float* __restrict__ Wg,
    const float* __restrict__ Whid, const float* __restrict__ Wd,
    __nv_bfloat16* __restrict__ oo, __nv_bfloat16* __restrict__ og,
    __nv_bfloat16* __restrict__ oh, __nv_bfloat16* __restrict__ od)
{
    if (blockIdx.z == 3) {
        const int j = blockIdx.y * 8 + blockIdx.x;   // 0..255
        #pragma unroll 4
        for (int t = 0; t < CVT_PER; t += 256) {
            int idx = j * CVT_PER + t + (int)threadIdx.x;
            const float* s;
            __nv_bfloat16* d;
            int loc;
            if (idx < 262144) { s = Wo; d = oo; loc = idx; }
            else {
                int k = idx - 262144;
                int m = k >> 20;
                loc = k & 0xFFFFF;
                s = (m == 0) ? Wg : (m == 1) ? Whid : Wd;
                d = (m == 0) ? og : (m == 1) ? oh : od;
            }
            float4 v = ((const float4*)s)[loc];
            __nv_bfloat162* dp = (__nv_bfloat162*)d + (size_t)loc * 2;
            dp[0] = __floats2bfloat162_rn(v.x, v.y);
            dp[1] = __floats2bfloat162_rn(v.z, v.w);
        }
        return;
    }

    extern __shared__ __nv_bfloat16 smh[];
    const unsigned as_u = smem_u32(smh);
    const __nv_bfloat16* B = (blockIdx.z == 0) ? B0 : (blockIdx.z == 1) ? B1 : B2;
    __half*              C = (blockIdx.z == 0) ? C0 : (blockIdx.z == 1) ? C1 : C2;
    const float sc = (blockIdx.z == 0) ? 0.125f * 1.4426950408889634f : 1.0f;
    const int tid = threadIdx.x, lane = tid & 31, warp = tid >> 5;
    const int wm = (warp >> 2) * 64, wn = (warp & 3) * 32;
    const int row0 = blockIdx.y * 128, col0 = blockIdx.x * 128;
    float acc[4][4][4];
    #pragma unroll
    for (int i = 0; i < 4; i++)
        #pragma unroll
        for (int j = 0; j < 4; j++)
            #pragma unroll
            for (int r = 0; r < 4; r++) acc[i][j][r] = 0.f;
    gemm_kloop<5, 4>(A + (size_t)row0 * K, B + col0, N, K,
                     as_u, as_u + 5 * ASTG4 * 2, acc, tid, lane, wm, wn);
    #pragma unroll
    for (int mf = 0; mf < 4; mf++) {
        const int r = row0 + wm + mf * 16 + (lane >> 2);
        #pragma unroll
        for (int nf = 0; nf < 4; nf++) {
            const int cc = col0 + wn + nf * 8 + (lane & 3) * 2;
            *(__half2*)(C + (size_t)r * N + cc) =
                __floats2half2_rn(acc[mf][nf][0] * sc, acc[mf][nf][1] * sc);
            *(__half2*)(C + (size_t)(r + 8) * N + cc) =
                __floats2half2_rn(acc[mf][nf][2] * sc, acc[mf][nf][3] * sc);
        }
    }
}

// ---------------- fused SwiGLU GEMM: hb = bf16(silu(A@Wg) * (A@Wh)) --------
__global__ void __launch_bounds__(256, 2) swiglu_gemm_kernel(
    const __nv_bfloat16* __restrict__ A,
    const __nv_bfloat16* __restrict__ Wg, const __nv_bfloat16* __restrict__ Wh,
    __nv_bfloat16* __restrict__ hb, int M, int N, int K)
{
    extern __shared__ __nv_bfloat16 smh[];
    const unsigned as_u = smem_u32(smh);
    const unsigned bs_u = as_u + 4 * ASTG4 * 2;
    unsigned* stash = (unsigned*)((char*)smh + 4 * STG4_B);

    const int tid = threadIdx.x, lane = tid & 31, warp = tid >> 5;
    const int wm = (warp >> 2) * 64, wn = (warp & 3) * 32;
    const int row0 = blockIdx.y * 128, col0 = blockIdx.x * 128;

    float acc[4][4][4];
    #pragma unroll
    for (int i = 0; i < 4; i++)
        #pragma unroll
        for (int j = 0; j < 4; j++)
            #pragma unroll
            for (int r = 0; r < 4; r++) acc[i][j][r] = 0.f;

    gemm_kloop<4, 4>(A + (size_t)row0 * K, Wg + col0, N, K,
                     as_u, bs_u, acc, tid, lane, wm, wn);

    unsigned* st = stash + tid * 33;
    #pragma unroll
    for (int mf = 0; mf < 4; mf++)
        #pragma unroll
        for (int nf = 0; nf < 4; nf++) {
            float s0 = acc[mf][nf][0]; s0 = s0 / (1.f + __expf(-s0));
            float s1 = acc[mf][nf][1]; s1 = s1 / (1.f + __expf(-s1));
            float s2 = acc[mf][nf][2]; s2 = s2 / (1.f + __expf(-s2));
            float s3 = acc[mf][nf][3]; s3 = s3 / (1.f + __expf(-s3));
            __nv_bfloat162 p0 = __floats2bfloat162_rn(s0, s1);
            __nv_bfloat162 p1 = __floats2bfloat162_rn(s2, s3);
            st[mf * 8 + nf * 2]     = *(unsigned*)&p0;
            st[mf * 8 + nf * 2 + 1] = *(unsigned*)&p1;
        }

    __syncthreads();

    #pragma unroll
    for (int i = 0; i < 4; i++)
        #pragma unroll
        for (int j = 0; j < 4; j++)
            #pragma unroll
            for (int r = 0; r < 4; r++) acc[i][j][r] = 0.f;

    gemm_kloop<4, 4>(A + (size_t)row0 * K, Wh + col0, N, K,
                     as_u, bs_u, acc, tid, lane, wm, wn);

    #pragma unroll
    for (int mf = 0; mf < 4; mf++) {
        const int r = row0 + wm + mf * 16 + (lane >> 2);
        #pragma unroll
        for (int nf = 0; nf < 4; nf++) {
            const int cc = col0 + wn + nf * 8 + (lane & 3) * 2;
            unsigned p0 = st[mf * 8 + nf * 2];
            unsigned p1 = st[mf * 8 + nf * 2 + 1];
            float g0 = __uint_as_float(p0 << 16);
            float g1 = __uint_as_float(p0 & 0xffff0000u);
            float g2 = __uint_as_float(p1 << 16);
            float g3 = __uint_as_float(p1 & 0xffff0000u);
            *(__nv_bfloat162*)(hb + (size_t)r * N + cc) =
                __floats2bfloat162_rn(g0 * acc[mf][nf][0], g1 * acc[mf][nf][1]);
            *(__nv_bfloat162*)(hb + (size_t)(r + 8) * N + cc) =
                __floats2bfloat162_rn(g2 * acc[mf][nf][2], g3 * acc[mf][nf][3]);
        }
    }
}

// ---------------- flash attention (f16 tensor path) ------------------------
#define QH 72
#define FQ_B (128 * QH * 2)
#define FK_B (64 * QH * 2)
#define FL_SMEM (FQ_B + 4 * FK_B)

__global__ void __launch_bounds__(256, 2) flash4_kernel(
    const __half* __restrict__ Qh, const __half* __restrict__ Kh,
    const __half* __restrict__ Vh, __nv_bfloat16* __restrict__ O)
{
    extern __shared__ char fsm[];
    const unsigned qs_u = smem_u32(fsm);
    const unsigned kb_u = qs_u + FQ_B;
    const unsigned vb_u = qs_u + FQ_B + 2 * FK_B;

    const int tid  = threadIdx.x;
    const int lane = tid & 31;
    const int warp = tid >> 5;
    const int bq = blockIdx.x, head = blockIdx.y, b = blockIdx.z;
    const size_t qtok0 = (size_t)b * SEQ + (size_t)bq * 128;
    const size_t ktokb = (size_t)b * SEQ;
    const int col0 = head * HD;
    const int m0 = warp * 16;

    #pragma unroll
    for (int j = 0; j < 4; j++) {
        int id = tid + j * 256;
        int r = id >> 3, c = (id & 7) * 8;
        cp16(qs_u + (r * QH + c) * 2, Qh + (qtok0 + r) * D_MODEL + col0 + c);
    }
    #pragma unroll
    for (int j = 0; j < 2; j++) {
        int id = tid + j * 256;
        int r = id >> 3, c = (id & 7) * 8;
        cp16(kb_u + (r * QH + c) * 2, Kh + (ktokb + r) * D_MODEL + col0 + c);
        cp16(vb_u + (r * QH + c) * 2, Vh + (ktokb + r) * D_MODEL + col0 + c);
    }
    CP_COMMIT();
    CP_WAIT0();
    __syncthreads();

    float m0s = -INFINITY, m1s = -INFINITY, l0s = 0.f, l1s = 0.f;
    float oacc[8][4];
    #pragma unroll
    for (int i = 0; i < 8; i++)
        #pragma unroll
        for (int j = 0; j < 4; j++) oacc[i][j] = 0.f;

    for (int kvt = 0; kvt < SEQ / 64; kvt++) {
        const int buf = kvt & 1;
        const bool pre = (kvt + 1) < SEQ / 64;
        if (pre) {
            const size_t kt = ktokb + (size_t)(kvt + 1) * 64;
            const unsigned kbd = kb_u + (buf ^ 1) * FK_B;
            const unsigned vbd = vb_u + (buf ^ 1) * FK_B;
            #pragma unroll
            for (int j = 0; j < 2; j++) {
                int id = tid + j * 256;
                int r = id >> 3, c = (id & 7) * 8;
                cp16(kbd + (r * QH + c) * 2, Kh + (kt + r) * D_MODEL + col0 + c);
                cp16(vbd + (r * QH + c) * 2, Vh + (kt + r) * D_MODEL + col0 + c);
            }
        }
        CP_COMMIT();

        float sacc[8][4];
        #pragma unroll
        for (int i = 0; i < 8; i++)
            #pragma unroll
            for (int j = 0; j < 4; j++) sacc[i][j] = 0.f;

        const unsigned kfb = kb_u + buf * FK_B;
        #pragma unroll
        for (int ks = 0; ks < 4; ks++) {
            const int k0 = ks * 16;
            unsigned a0, a1, a2, a3;
            ldsm_x4(a0, a1, a2, a3,
                    qs_u + ((m0 + (lane & 15)) * QH + k0 + (lane >> 4) * 8) * 2);
            #pragma unroll
            for (int ng = 0; ng < 4; ng++) {
                unsigned b0, b1, b2, b3;
                ldsm_x4(b0, b1, b2, b3,
                        kfb + ((ng * 16 + (lane & 15)) * QH + k0 + (lane >> 4) * 8) * 2);
                mma_f16(sacc[ng * 2],     a0, a1, a2, a3, b0, b2);
                mma_f16(sacc[ng * 2 + 1], a0, a1, a2, a3, b1, b3);
            }
        }

        float mx0 = -INFINITY, mx1 = -INFINITY;
        #pragma unroll
        for (int nf = 0; nf < 8; nf++) {
            mx0 = fmaxf(mx0, fmaxf(sacc[nf][0], sacc[nf][1]));
            mx1 = fmaxf(mx1, fmaxf(sacc[nf][2], sacc[nf][3]));
        }
        mx0 = fmaxf(mx0, __shfl_xor_sync(0xffffffffu, mx0, 1));
        mx0 = fmaxf(mx0, __shfl_xor_sync(0xffffffffu, mx0, 2));
        mx1 = fmaxf(mx1, __shfl_xor_sync(0xffffffffu, mx1, 1));
        mx1 = fmaxf(mx1, __shfl_xor_sync(0xffffffffu, mx1, 2));

        const float mn0 = fmaxf(m0s, mx0);
        const float mn1 = fmaxf(m1s, mx1);
        const float al0 = ex2f(m0s - mn0);
        const float al1 = ex2f(m1s - mn1);

        unsigned pa0[8], pa1[8];
        float ls0 = 0.f, ls1 = 0.f;
        #pragma unroll
        for (int nf = 0; nf < 8; nf++) {
            float p0 = ex2f(sacc[nf][0] - mn0);
            float p1 = ex2f(sacc[nf][1] - mn0);
            float p2 = ex2f(sacc[nf][2] - mn1);
            float p3 = ex2f(sacc[nf][3] - mn1);
            ls0 += p0 + p1;
            ls1 += p2 + p3;
            pa0[nf] = packh2(p0, p1);
            pa1[nf] = packh2(p2, p3);
        }
        ls0 += __shfl_xor_sync(0xffffffffu, ls0, 1);
        ls0 += __shfl_xor_sync(0xffffffffu, ls0, 2);
        ls1 += __shfl_xor_sync(0xffffffffu, ls1, 1);
        ls1 += __shfl_xor_sync(0xffffffffu, ls1, 2);
        l0s = l0s * al0 + ls0;
        l1s = l1s * al1 + ls1;
        m0s = mn0; m1s = mn1;

        #pragma unroll
        for (int nf = 0; nf < 8; nf++) {
            oacc[nf][0] *= al0; oacc[nf][1] *= al0;
            oacc[nf][2] *= al1; oacc[nf][3] *= al1;
        }

        const unsigned vhb = vb_u + buf * FK_B;
        #pragma unroll
        for (int ks = 0; ks < 4; ks++) {
            unsigned a0 = pa0[2 * ks],     a1 = pa1[2 * ks];
            unsigned a2 = pa0[2 * ks + 1], a3 = pa1[2 * ks + 1];
            #pragma unroll
            for (int no = 0; no < 4; no++) {
                unsigned addr = vhb +
                    ((ks * 16 + (lane & 15)) * QH + no * 16 + (lane >> 4) * 8) * 2;
                unsigned b0, b1, b2, b3;
                ldsm_x4_t(b0, b1, b2, b3, addr);
                mma_f16(oacc[no * 2],     a0, a1, a2, a3, b0, b1);
                mma_f16(oacc[no * 2 + 1], a0, a1, a2, a3, b2, b3);
            }
        }

        CP_WAIT0();
        __syncthreads();
    }

    const float i0 = 1.f / l0s;
    const float i1 = 1.f / l1s;
    const size_t row0 = qtok0 + m0 + (lane >> 2);
    #pragma unroll
    for (int no = 0; no < 8; no++) {
        const int cw = col0 + no * 8 + (lane & 3) * 2;
        *(__nv_bfloat162*)(O + row0 * D_MODEL + cw) =
            __floats2bfloat162_rn(oacc[no][0] * i0, oacc[no][1] * i0);
        *(__nv_bfloat162*)(O + (row0 + 8) * D_MODEL + cw) =
            __floats2bfloat162_rn(oacc[no][2] * i1, oacc[no][3] * i1);
    }
}

// ---------------- driver ----------------------------------------------------
extern "C" void kernel_launch(void* const* d_in, const int* in_sizes, int n_in,
                              void* d_out, int out_size)
{
    const float* x       = (const float*)d_in[0];
    const float* W_q     = (const float*)d_in[1];
    const float* W_k     = (const float*)d_in[2];
    const float* W_v     = (const float*)d_in[3];
    const float* W_o     = (const float*)d_in[4];
    const float* b_o     = (const float*)d_in[5];
    const float* a_nw    = (const float*)d_in[6];
    const float* f_nw    = (const float*)d_in[7];
    const float* W_gate  = (const float*)d_in[8];
    const float* W_hid   = (const float*)d_in[9];
    const float* W_out   = (const float*)d_in[10];
    const float* b_out   = (const float*)d_in[11];
    float* out = (float*)d_out;

    float *x1;
    __half *qh, *kh, *vh;
    __nv_bfloat16 *xnb, *atb, *hb, *wq, *wk, *wv, *wo, *wg, *wh, *wd;
    cudaGetSymbolAddress((void**)&qh,  g_qh);
    cudaGetSymbolAddress((void**)&kh,  g_kh);
    cudaGetSymbolAddress((void**)&vh,  g_vh);
    cudaGetSymbolAddress((void**)&x1,  g_x1);
    cudaGetSymbolAddress((void**)&xnb, g_xnb);
    cudaGetSymbolAddress((void**)&atb, g_atb);
    cudaGetSymbolAddress((void**)&hb,  g_hb);
    cudaGetSymbolAddress((void**)&wq,  g_wq);
    cudaGetSymbolAddress((void**)&wk,  g_wk);
    cudaGetSymbolAddress((void**)&wv,  g_wv);
    cudaGetSymbolAddress((void**)&wo,  g_wo);
    cudaGetSymbolAddress((void**)&wg,  g_wg);
    cudaGetSymbolAddress((void**)&wh,  g_wh);
    cudaGetSymbolAddress((void**)&wd,  g_wd);

    cudaFuncSetAttribute(flash4_kernel,
                         cudaFuncAttributeMaxDynamicSharedMemorySize, FL_SMEM);
    cudaFuncSetAttribute(mma_gemm_kernel<4>,
                         cudaFuncAttributeMaxDynamicSharedMemorySize, G5_SMEM_M128);
    cudaFuncSetAttribute(mma_gemm_kernel<2>,
                         cudaFuncAttributeMaxDynamicSharedMemorySize, G5_SMEM_M64);
    cudaFuncSetAttribute(mma_gemm_qkv,
                         cudaFuncAttributeMaxDynamicSharedMemorySize, G5_SMEM_M128);
    cudaFuncSetAttribute(swiglu_gemm_kernel,
                         cudaFuncAttributeMaxDynamicSharedMemorySize, SWI_SMEM);

    // 1) QKV weight cvt + attn rmsnorm, one launch
    prep_kernel<<<7168, 256>>>(x, a_nw, xnb, W_q, W_k, W_v, wq, wk, wv);

    // 2) q, k, v projections + weight conversion plane (z==3 fills tail)
    dim3 gqkv(D_MODEL / 128, N_TOK / 128, 4);
    mma_gemm_qkv<<<gqkv, 256, G5_SMEM_M128>>>(xnb, wq, wk, wv, qh, kh, vh,
                                              N_TOK, D_MODEL, D_MODEL,
                                              W_o, W_gate, W_hid, W_out,
                                              wo, wg, wh, wd);

    // 3) attention -> bf16
    dim3 ga(SEQ / 128, N_HEADS, 2);
    flash4_kernel<<<ga, 256, FL_SMEM>>>(qh, kh, vh, atb);

    // 4) output projection + bias + residual (M=64 tiles: full chip)
    dim3 go(D_MODEL / 128, N_TOK / 64);
    mma_gemm_kernel<2><<<go, 256, G5_SMEM_M64>>>(atb, wo, b_o, x, x1,
                                                 N_TOK, D_MODEL, D_MODEL);

    // 5) ffn rmsnorm -> bf16
    rmsnorm_kernel<<<N_TOK, 256>>>(x1, f_nw, xnb);

    // 6+7) fused gate/hidden GEMMs + SwiGLU -> hb bf16
    dim3 gf(D_FF / 128, N_TOK / 128);
    swiglu_gemm_kernel<<<gf, 256, SWI_SMEM>>>(xnb, wg, wh, hb,
                                              N_TOK, D_FF, D_MODEL);

    // 8) down projection + bias + residual -> out
    dim3 gd(D_MODEL / 128, N_TOK / 128);
    mma_gemm_kernel<4><<<gd, 256, G5_SMEM_M128>>>(hb, wd, b_out, x1, out,
                                                  N_TOK, D_MODEL, D_FF);
}

// round 13
// speedup vs baseline: 1.0081x; 1.0022x over previous
#include <cuda_runtime.h>
#include <cuda_fp16.h>
#include <cuda_bf16.h>
#include <math.h>

#define D_MODEL 1024
#define N_TOK   4096
#define N_HEADS 16
#define HD      64
#define D_FF    4096
#define SEQ     2048

// ---------------- scratch (device globals; no allocation allowed) ----------
__device__ __half g_qh[N_TOK * D_MODEL];
__device__ __half g_kh[N_TOK * D_MODEL];
__device__ __half g_vh[N_TOK * D_MODEL];
__device__ float  g_x1[N_TOK * D_MODEL];
__device__ __nv_bfloat16 g_xnb[N_TOK * D_MODEL];
__device__ __nv_bfloat16 g_atb[N_TOK * D_MODEL];
__device__ __nv_bfloat16 g_hb [N_TOK * D_FF];
__device__ __nv_bfloat16 g_wq[D_MODEL * D_MODEL];
__device__ __nv_bfloat16 g_wk[D_MODEL * D_MODEL];
__device__ __nv_bfloat16 g_wv[D_MODEL * D_MODEL];
__device__ __nv_bfloat16 g_wo[D_MODEL * D_MODEL];
__device__ __nv_bfloat16 g_wg[D_MODEL * D_FF];
__device__ __nv_bfloat16 g_wh[D_MODEL * D_FF];
__device__ __nv_bfloat16 g_wd[D_FF * D_MODEL];

// ---------------- helpers ---------------------------------------------------
__device__ __forceinline__ unsigned smem_u32(const void* p) {
    unsigned a;
    asm("{ .reg .u64 t; cvta.to.shared.u64 t, %1; cvt.u32.u64 %0, t; }"
        : "=r"(a) : "l"(p));
    return a;
}
__device__ __forceinline__ float ex2f(float x) {
    float y;
    asm("ex2.approx.ftz.f32 %0, %1;" : "=f"(y) : "f"(x));
    return y;
}
__device__ __forceinline__ unsigned packh2(float lo, float hi) {
    unsigned d;
    asm("cvt.rn.f16x2.f32 %0, %1, %2;" : "=r"(d) : "f"(hi), "f"(lo));
    return d;
}
__device__ __forceinline__ void ldsm_x4(unsigned& r0, unsigned& r1,
                                        unsigned& r2, unsigned& r3, unsigned addr) {
    asm volatile("ldmatrix.sync.aligned.m8n8.x4.shared.b16 {%0,%1,%2,%3}, [%4];"
                 : "=r"(r0), "=r"(r1), "=r"(r2), "=r"(r3) : "r"(addr));
}
__device__ __forceinline__ void ldsm_x4_t(unsigned& r0, unsigned& r1,
                                          unsigned& r2, unsigned& r3, unsigned addr) {
    asm volatile("ldmatrix.sync.aligned.m8n8.x4.trans.shared.b16 {%0,%1,%2,%3}, [%4];"
                 : "=r"(r0), "=r"(r1), "=r"(r2), "=r"(r3) : "r"(addr));
}
__device__ __forceinline__ void mma_f16(float* d, unsigned a0, unsigned a1,
                                        unsigned a2, unsigned a3,
                                        unsigned b0, unsigned b1) {
    asm volatile(
        "mma.sync.aligned.m16n8k16.row.col.f32.f16.f16.f32 "
        "{%0,%1,%2,%3}, {%4,%5,%6,%7}, {%8,%9}, {%0,%1,%2,%3};"
        : "+f"(d[0]), "+f"(d[1]), "+f"(d[2]), "+f"(d[3])
        : "r"(a0), "r"(a1), "r"(a2), "r"(a3), "r"(b0), "r"(b1));
}
__device__ __forceinline__ void mma_bf16(float* d, unsigned a0, unsigned a1,
                                         unsigned a2, unsigned a3,
                                         unsigned b0, unsigned b1) {
    asm volatile(
        "mma.sync.aligned.m16n8k16.row.col.f32.bf16.bf16.f32 "
        "{%0,%1,%2,%3}, {%4,%5,%6,%7}, {%8,%9}, {%0,%1,%2,%3};"
        : "+f"(d[0]), "+f"(d[1]), "+f"(d[2]), "+f"(d[3])
        : "r"(a0), "r"(a1), "r"(a2), "r"(a3), "r"(b0), "r"(b1));
}
__device__ __forceinline__ void cp16(unsigned dst, const void* src) {
    asm volatile("cp.async.cg.shared.global [%0], [%1], 16;"
                 :: "r"(dst), "l"(src));
}
#define CP_COMMIT() asm volatile("cp.async.commit_group;")
#define CP_WAIT0()  asm volatile("cp.async.wait_group 0;")

// ---------------- prep kernel: QKV/O weight cvt + rmsnorm1 -----------------
// blocks [0,4096): convert wq/wk/wv/wo (1024 blocks each)
// blocks [4096,8192): rmsnorm row (bx - 4096)
__global__ void __launch_bounds__(256) prep_kernel(
    const float* __restrict__ x, const float* __restrict__ a_nw,
    __nv_bfloat16* __restrict__ xnb,
    const float* __restrict__ Wq, const float* __restrict__ Wk,
    const float* __restrict__ Wv, const float* __restrict__ Wo,
    __nv_bfloat16* oq, __nv_bfloat16* ok, __nv_bfloat16* ov, __nv_bfloat16* oo)
{
    const int bx = blockIdx.x;
    const int t  = threadIdx.x;
    __shared__ float red[8];

    if (bx < 4096) {
        const int z = bx >> 10;
        const float* s = (z == 0) ? Wq : (z == 1) ? Wk : (z == 2) ? Wv : Wo;
        __nv_bfloat16* d = (z == 0) ? oq : (z == 1) ? ok : (z == 2) ? ov : oo;
        size_t i = (size_t)(bx & 1023) * 256 + t;
        float4 v = ((const float4*)s)[i];
        __nv_bfloat162* dp = (__nv_bfloat162*)d + i * 2;
        dp[0] = __floats2bfloat162_rn(v.x, v.y);
        dp[1] = __floats2bfloat162_rn(v.z, v.w);
        return;
    }

    const int row = bx - 4096;
    const float4* xr = (const float4*)(x + (size_t)row * D_MODEL);
    float4 v = xr[t];
    float ss = v.x * v.x + v.y * v.y + v.z * v.z + v.w * v.w;
    #pragma unroll
    for (int m = 16; m; m >>= 1) ss += __shfl_xor_sync(0xffffffffu, ss, m);
    if ((t & 31) == 0) red[t >> 5] = ss;
    __syncthreads();
    float tot = 0.f;
    #pragma unroll
    for (int i = 0; i < 8; i++) tot += red[i];
    float r = rsqrtf(tot * (1.0f / D_MODEL) + 1e-6f);
    float4 wv = ((const float4*)a_nw)[t];
    __nv_bfloat162* yr = (__nv_bfloat162*)(xnb + (size_t)row * D_MODEL) + t * 2;
    yr[0] = __floats2bfloat162_rn(v.x * wv.x * r, v.y * wv.y * r);
    yr[1] = __floats2bfloat162_rn(v.z * wv.z * r, v.w * wv.w * r);
}

// ---------------- rmsnorm (standalone, second norm) ------------------------
__global__ void __launch_bounds__(256) rmsnorm_kernel(
    const float* __restrict__ x, const float* __restrict__ w,
    __nv_bfloat16* __restrict__ y)
{
    int row = blockIdx.x;
    int t   = threadIdx.x;
    const float4* xr = (const float4*)(x + (size_t)row * D_MODEL);
    float4 v = xr[t];
    float ss = v.x * v.x + v.y * v.y + v.z * v.z + v.w * v.w;
    #pragma unroll
    for (int m = 16; m; m >>= 1) ss += __shfl_xor_sync(0xffffffffu, ss, m);
    __shared__ float red[8];
    if ((t & 31) == 0) red[t >> 5] = ss;
    __syncthreads();
    float tot = 0.f;
    #pragma unroll
    for (int i = 0; i < 8; i++) tot += red[i];
    float r = rsqrtf(tot * (1.0f / D_MODEL) + 1e-6f);
    float4 wv = ((const float4*)w)[t];
    __nv_bfloat162* yr = (__nv_bfloat162*)(y + (size_t)row * D_MODEL) + t * 2;
    yr[0] = __floats2bfloat162_rn(v.x * wv.x * r, v.y * wv.y * r);
    yr[1] = __floats2bfloat162_rn(v.z * wv.z * r, v.w * wv.w * r);
}

// ---------------- bf16 HMMA GEMM core, templated M (MF*32 rows) ------------
#define BKh 32
#define SAh 40
#define SBh 136
#define BSTG (BKh * SBh)
#define ASTG4 (128 * SAh)
#define STG4_B ((ASTG4 + BSTG) * 2)
#define G5_SMEM_M128 ((ASTG4 + BSTG) * 2 * 5)           // 94720
#define G5_SMEM_M64  (((64 * SAh) + BSTG) * 2 * 5)      // 69120
#define SWI_STASH (256 * 33 * 4)
#define SWI_SMEM (4 * STG4_B + SWI_STASH)               // 109568

template<int NSTG, int MF>
__device__ __forceinline__ void gemm_kloop(
    const __nv_bfloat16* __restrict__ Ab,
    const __nv_bfloat16* __restrict__ Bb,
    int N, int K, unsigned as_u, unsigned bs_u,
    float (&acc)[MF][4][4], int tid, int lane, int wm, int wn)
{
    constexpr int AST = MF * 32 * SAh;
    const int KC = K / BKh;

    #define LOAD_STAGE(S, C)                                                   \
        do {                                                                   \
            _Pragma("unroll")                                                  \
            for (int t_ = 0; t_ < MF * 128; t_ += 256) {                       \
                int seg = tid + t_;                                            \
                int row_ = seg >> 2, colh_ = (seg & 3) * 8;                    \
                cp16(as_u + ((S) * AST + row_ * SAh + colh_) * 2,              \
                     Ab + (size_t)row_ * K + (C) * BKh + colh_);               \
            }                                                                  \
            _Pragma("unroll")                                                  \
            for (int t_ = 0; t_ < 512; t_ += 256) {                            \
                int seg = tid + t_;                                            \
                int row_ = seg >> 4, colh_ = (seg & 15) * 8;                   \
                cp16(bs_u + ((S) * BSTG + row_ * SBh + colh_) * 2,             \
                     Bb + (size_t)((C) * BKh + row_) * N + colh_);             \
            }                                                                  \
        } while (0)

    #pragma unroll
    for (int s = 0; s < NSTG - 1; s++) {
        LOAD_STAGE(s, s);
        CP_COMMIT();
    }

    for (int c = 0; c < KC; c++) {
        asm volatile("cp.async.wait_group %0;" :: "n"(NSTG - 2));
        __syncthreads();

        if (c + NSTG - 1 < KC) {
            const int s = (c + NSTG - 1) % NSTG;
            LOAD_STAGE(s, c + NSTG - 1);
        }
        CP_COMMIT();

        const int s = c % NSTG;
        const unsigned asb = as_u + s * AST * 2;
        const unsigned bsb = bs_u + s * BSTG * 2;
        #pragma unroll
        for (int ks = 0; ks < 2; ks++) {
            const int k0 = ks * 16;
            unsigned a[MF][4];
            #pragma unroll
            for (int mf = 0; mf < MF; mf++) {
                unsigned addr = asb +
                    ((wm + mf * 16 + (lane & 15)) * SAh + k0 + (lane >> 4) * 8) * 2;
                ldsm_x4(a[mf][0], a[mf][1], a[mf][2], a[mf][3], addr);
            }
            unsigned b[2][4];
            #pragma unroll
            for (int nb = 0; nb < 2; nb++) {
                unsigned addr = bsb +
                    ((k0 + (lane & 15)) * SBh + wn + nb * 16 + (lane >> 4) * 8) * 2;
                ldsm_x4_t(b[nb][0], b[nb][1], b[nb][2], b[nb][3], addr);
            }
            #pragma unroll
            for (int mf = 0; mf < MF; mf++)
                #pragma unroll
                for (int nf = 0; nf < 4; nf++)
                    mma_bf16(acc[mf][nf], a[mf][0], a[mf][1], a[mf][2], a[mf][3],
                             b[nf >> 1][(nf & 1) * 2], b[nf >> 1][(nf & 1) * 2 + 1]);
        }
    }
    #undef LOAD_STAGE
}

template<int MF>
__device__ __forceinline__ void gemm_epilogue(
    float (&acc)[MF][4][4], const float* bias, const float* res,
    float* C, int N, int row0, int col0, int lane, int wm, int wn)
{
    #pragma unroll
    for (int mf = 0; mf < MF; mf++) {
        const int r = row0 + wm + mf * 16 + (lane >> 2);
        #pragma unroll
        for (int nf = 0; nf < 4; nf++) {
            const int cc = col0 + wn + nf * 8 + (lane & 3) * 2;
            float2 v0 = make_float2(acc[mf][nf][0], acc[mf][nf][1]);
            float2 v1 = make_float2(acc[mf][nf][2], acc[mf][nf][3]);
            if (bias) {
                float2 bv = *(const float2*)(bias + cc);
                v0.x += bv.x; v0.y += bv.y;
                v1.x += bv.x; v1.y += bv.y;
            }
            if (res) {
                float2 r0 = *(const float2*)(res + (size_t)r * N + cc);
                float2 r1 = *(const float2*)(res + (size_t)(r + 8) * N + cc);
                v0.x += r0.x; v0.y += r0.y;
                v1.x += r1.x; v1.y += r1.y;
            }
            *(float2*)(C + (size_t)r * N + cc) = v0;
            *(float2*)(C + (size_t)(r + 8) * N + cc) = v1;
        }
    }
}

// generic GEMM kernel (bias+res), templated on MF
template<int MF>
__global__ void __launch_bounds__(256, 2) mma_gemm_kernel(
    const __nv_bfloat16* __restrict__ A, const __nv_bfloat16* __restrict__ B,
    const float* __restrict__ bias, const float* __restrict__ res,
    float* __restrict__ C, int M, int N, int K)
{
    extern __shared__ __nv_bfloat16 smh[];
    const unsigned as_u = smem_u32(smh);
    const int tid = threadIdx.x, lane = tid & 31, warp = tid >> 5;
    const int wm = (warp >> 2) * (MF * 16), wn = (warp & 3) * 32;
    const int row0 = blockIdx.y * (MF * 32), col0 = blockIdx.x * 128;
    float acc[MF][4][4];
    #pragma unroll
    for (int i = 0; i < MF; i++)
        #pragma unroll
        for (int j = 0; j < 4; j++)
            #pragma unroll
            for (int r = 0; r < 4; r++) acc[i][j][r] = 0.f;
    gemm_kloop<5, MF>(A + (size_t)row0 * K, B + col0, N, K,
                      as_u, as_u + 5 * (MF * 32 * SAh) * 2, acc, tid, lane, wm, wn);
    gemm_epilogue<MF>(acc, bias, res, C, N, row0, col0, lane, wm, wn);
}

// QKV projections (z<3) + FFN weight conversion plane (z==3).
#define CVT_F4    (3 * 1024 * 1024)
#define CVT_PER   (CVT_F4 / 256)

__global__ void __launch_bounds__(256, 2) mma_gemm_qkv(
    const __nv_bfloat16* __restrict__ A,
    const __nv_bfloat16* __restrict__ B0, const __nv_bfloat16* __restrict__ B1,
    const __nv_bfloat16* __restrict__ B2,
    __half* __restrict__ C0, __half* __restrict__ C1, __half* __restrict__ C2,
    int M, int N, int K,
    const float* __restrict__ Wg, const float* __restrict__ Whid,
    const float* __restrict__ Wd,
    __nv_bfloat16* __restrict__ og, __nv_bfloat16* __restrict__ oh,
    __nv_bfloat16* __restrict__ od)
{
    if (blockIdx.z == 3) {
        const int j = blockIdx.y * 8 + blockIdx.x;   // 0..255
        #pragma unroll 4
        for (int t = 0; t < CVT_PER; t += 256) {
            int idx = j * CVT_PER + t + (int)threadIdx.x;
            int m   = idx >> 20;
            int loc = idx & 0xFFFFF;
            const float* s = (m == 0) ? Wg : (m == 1) ? Whid : Wd;
            __nv_bfloat16* d = (m == 0) ? og : (m == 1) ? oh : od;
            float4 v = ((const float4*)s)[loc];
            __nv_bfloat162* dp = (__nv_bfloat162*)d + (size_t)loc * 2;
            dp[0] = __floats2bfloat162_rn(v.x, v.y);
            dp[1] = __floats2bfloat162_rn(v.z, v.w);
        }
        return;
    }

    extern __shared__ __nv_bfloat16 smh[];
    const unsigned as_u = smem_u32(smh);
    const __nv_bfloat16* B = (blockIdx.z == 0) ? B0 : (blockIdx.z == 1) ? B1 : B2;
    __half*              C = (blockIdx.z == 0) ? C0 : (blockIdx.z == 1) ? C1 : C2;
    const float sc = (blockIdx.z == 0) ? 0.125f * 1.4426950408889634f : 1.0f;
    const int tid = threadIdx.x, lane = tid & 31, warp = tid >> 5;
    const int wm = (warp >> 2) * 64, wn = (warp & 3) * 32;
    const int row0 = blockIdx.y * 128, col0 = blockIdx.x * 128;
    float acc[4][4][4];
    #pragma unroll
    for (int i = 0; i < 4; i++)
        #pragma unroll
        for (int j = 0; j < 4; j++)
            #pragma unroll
            for (int r = 0; r < 4; r++) acc[i][j][r] = 0.f;
    gemm_kloop<5, 4>(A + (size_t)row0 * K, B + col0, N, K,
                     as_u, as_u + 5 * ASTG4 * 2, acc, tid, lane, wm, wn);
    #pragma unroll
    for (int mf = 0; mf < 4; mf++) {
        const int r = row0 + wm + mf * 16 + (lane >> 2);
        #pragma unroll
        for (int nf = 0; nf < 4; nf++) {
            const int cc = col0 + wn + nf * 8 + (lane & 3) * 2;
            *(__half2*)(C + (size_t)r * N + cc) =
                __floats2half2_rn(acc[mf][nf][0] * sc, acc[mf][nf][1] * sc);
            *(__half2*)(C + (size_t)(r + 8) * N + cc) =
                __floats2half2_rn(acc[mf][nf][2] * sc, acc[mf][nf][3] * sc);
        }
    }
}

// ---------------- fused SwiGLU GEMM: hb = bf16(silu(A@Wg) * (A@Wh)) --------
__global__ void __launch_bounds__(256, 2) swiglu_gemm_kernel(
    const __nv_bfloat16* __restrict__ A,
    const __nv_bfloat16* __restrict__ Wg, const __nv_bfloat16* __restrict__ Wh,
    __nv_bfloat16* __restrict__ hb, int M, int N, int K)
{
    extern __shared__ __nv_bfloat16 smh[];
    const unsigned as_u = smem_u32(smh);
    const unsigned bs_u = as_u + 4 * ASTG4 * 2;
    unsigned* stash = (unsigned*)((char*)smh + 4 * STG4_B);

    const int tid = threadIdx.x, lane = tid & 31, warp = tid >> 5;
    const int wm = (warp >> 2) * 64, wn = (warp & 3) * 32;
    const int row0 = blockIdx.y * 128, col0 = blockIdx.x * 128;

    float acc[4][4][4];
    #pragma unroll
    for (int i = 0; i < 4; i++)
        #pragma unroll
        for (int j = 0; j < 4; j++)
            #pragma unroll
            for (int r = 0; r < 4; r++) acc[i][j][r] = 0.f;

    gemm_kloop<4, 4>(A + (size_t)row0 * K, Wg + col0, N, K,
                     as_u, bs_u, acc, tid, lane, wm, wn);

    unsigned* st = stash + tid * 33;
    #pragma unroll
    for (int mf = 0; mf < 4; mf++)
        #pragma unroll
        for (int nf = 0; nf < 4; nf++) {
            float s0 = acc[mf][nf][0]; s0 = s0 / (1.f + __expf(-s0));
            float s1 = acc[mf][nf][1]; s1 = s1 / (1.f + __expf(-s1));
            float s2 = acc[mf][nf][2]; s2 = s2 / (1.f + __expf(-s2));
            float s3 = acc[mf][nf][3]; s3 = s3 / (1.f + __expf(-s3));
            __nv_bfloat162 p0 = __floats2bfloat162_rn(s0, s1);
            __nv_bfloat162 p1 = __floats2bfloat162_rn(s2, s3);
            st[mf * 8 + nf * 2]     = *(unsigned*)&p0;
            st[mf * 8 + nf * 2 + 1] = *(unsigned*)&p1;
        }

    __syncthreads();

    #pragma unroll
    for (int i = 0; i < 4; i++)
        #pragma unroll
        for (int j = 0; j < 4; j++)
            #pragma unroll
            for (int r = 0; r < 4; r++) acc[i][j][r] = 0.f;

    gemm_kloop<4, 4>(A + (size_t)row0 * K, Wh + col0, N, K,
                     as_u, bs_u, acc, tid, lane, wm, wn);

    #pragma unroll
    for (int mf = 0; mf < 4; mf++) {
        const int r = row0 + wm + mf * 16 + (lane >> 2);
        #pragma unroll
        for (int nf = 0; nf < 4; nf++) {
            const int cc = col0 + wn + nf * 8 + (lane & 3) * 2;
            unsigned p0 = st[mf * 8 + nf * 2];
            unsigned p1 = st[mf * 8 + nf * 2 + 1];
            float g0 = __uint_as_float(p0 << 16);
            float g1 = __uint_as_float(p0 & 0xffff0000u);
            float g2 = __uint_as_float(p1 << 16);
            float g3 = __uint_as_float(p1 & 0xffff0000u);
            *(__nv_bfloat162*)(hb + (size_t)r * N + cc) =
                __floats2bfloat162_rn(g0 * acc[mf][nf][0], g1 * acc[mf][nf][1]);
            *(__nv_bfloat162*)(hb + (size_t)(r + 8) * N + cc) =
                __floats2bfloat162_rn(g2 * acc[mf][nf][2], g3 * acc[mf][nf][3]);
        }
    }
}

// ---------------- flash attention (f16 tensor path) ------------------------
#define QH 72
#define FQ_B (128 * QH * 2)
#define FK_B (64 * QH * 2)
#define FL_SMEM (FQ_B + 4 * FK_B)

__global__ void __launch_bounds__(256, 2) flash4_kernel(
    const __half* __restrict__ Qh, const __half* __restrict__ Kh,
    const __half* __restrict__ Vh, __nv_bfloat16* __restrict__ O)
{
    extern __shared__ char fsm[];
    const unsigned qs_u = smem_u32(fsm);
    const unsigned kb_u = qs_u + FQ_B;
    const unsigned vb_u = qs_u + FQ_B + 2 * FK_B;

    const int tid  = threadIdx.x;
    const int lane = tid & 31;
    const int warp = tid >> 5;
    const int bq = blockIdx.x, head = blockIdx.y, b = blockIdx.z;
    const size_t qtok0 = (size_t)b * SEQ + (size_t)bq * 128;
    const size_t ktokb = (size_t)b * SEQ;
    const int col0 = head * HD;
    const int m0 = warp * 16;

    #pragma unroll
    for (int j = 0; j < 4; j++) {
        int id = tid + j * 256;
        int r = id >> 3, c = (id & 7) * 8;
        cp16(qs_u + (r * QH + c) * 2, Qh + (qtok0 + r) * D_MODEL + col0 + c);
    }
    #pragma unroll
    for (int j = 0; j < 2; j++) {
        int id = tid + j * 256;
        int r = id >> 3, c = (id & 7) * 8;
        cp16(kb_u + (r * QH + c) * 2, Kh + (ktokb + r) * D_MODEL + col0 + c);
        cp16(vb_u + (r * QH + c) * 2, Vh + (ktokb + r) * D_MODEL + col0 + c);
    }
    CP_COMMIT();
    CP_WAIT0();
    __syncthreads();

    float m0s = -INFINITY, m1s = -INFINITY, l0s = 0.f, l1s = 0.f;
    float oacc[8][4];
    #pragma unroll
    for (int i = 0; i < 8; i++)
        #pragma unroll
        for (int j = 0; j < 4; j++) oacc[i][j] = 0.f;

    for (int kvt = 0; kvt < SEQ / 64; kvt++) {
        const int buf = kvt & 1;
        const bool pre = (kvt + 1) < SEQ / 64;
        if (pre) {
            const size_t kt = ktokb + (size_t)(kvt + 1) * 64;
            const unsigned kbd = kb_u + (buf ^ 1) * FK_B;
            const unsigned vbd = vb_u + (buf ^ 1) * FK_B;
            #pragma unroll
            for (int j = 0; j < 2; j++) {
                int id = tid + j * 256;
                int r = id >> 3, c = (id & 7) * 8;
                cp16(kbd + (r * QH + c) * 2, Kh + (kt + r) * D_MODEL + col0 + c);
                cp16(vbd + (r * QH + c) * 2, Vh + (kt + r) * D_MODEL + col0 + c);
            }
        }
        CP_COMMIT();

        float sacc[8][4];
        #pragma unroll
        for (int i = 0; i < 8; i++)
            #pragma unroll
            for (int j = 0; j < 4; j++) sacc[i][j] = 0.f;

        const unsigned kfb = kb_u + buf * FK_B;
        #pragma unroll
        for (int ks = 0; ks < 4; ks++) {
            const int k0 = ks * 16;
            unsigned a0, a1, a2, a3;
            ldsm_x4(a0, a1, a2, a3,
                    qs_u + ((m0 + (lane & 15)) * QH + k0 + (lane >> 4) * 8) * 2);
            #pragma unroll
            for (int ng = 0; ng < 4; ng++) {
                unsigned b0, b1, b2, b3;
                ldsm_x4(b0, b1, b2, b3,
                        kfb + ((ng * 16 + (lane & 15)) * QH + k0 + (lane >> 4) * 8) * 2);
                mma_f16(sacc[ng * 2],     a0, a1, a2, a3, b0, b2);
                mma_f16(sacc[ng * 2 + 1], a0, a1, a2, a3, b1, b3);
            }
        }

        float mx0 = -INFINITY, mx1 = -INFINITY;
        #pragma unroll
        for (int nf = 0; nf < 8; nf++) {
            mx0 = fmaxf(mx0, fmaxf(sacc[nf][0], sacc[nf][1]));
            mx1 = fmaxf(mx1, fmaxf(sacc[nf][2], sacc[nf][3]));
        }
        mx0 = fmaxf(mx0, __shfl_xor_sync(0xffffffffu, mx0, 1));
        mx0 = fmaxf(mx0, __shfl_xor_sync(0xffffffffu, mx0, 2));
        mx1 = fmaxf(mx1, __shfl_xor_sync(0xffffffffu, mx1, 1));
        mx1 = fmaxf(mx1, __shfl_xor_sync(0xffffffffu, mx1, 2));

        const float mn0 = fmaxf(m0s, mx0);
        const float mn1 = fmaxf(m1s, mx1);
        const float al0 = ex2f(m0s - mn0);
        const float al1 = ex2f(m1s - mn1);

        unsigned pa0[8], pa1[8];
        float ls0 = 0.f, ls1 = 0.f;
        #pragma unroll
        for (int nf = 0; nf < 8; nf++) {
            float p0 = ex2f(sacc[nf][0] - mn0);
            float p1 = ex2f(sacc[nf][1] - mn0);
            float p2 = ex2f(sacc[nf][2] - mn1);
            float p3 = ex2f(sacc[nf][3] - mn1);
            ls0 += p0 + p1;
            ls1 += p2 + p3;
            pa0[nf] = packh2(p0, p1);
            pa1[nf] = packh2(p2, p3);
        }
        ls0 += __shfl_xor_sync(0xffffffffu, ls0, 1);
        ls0 += __shfl_xor_sync(0xffffffffu, ls0, 2);
        ls1 += __shfl_xor_sync(0xffffffffu, ls1, 1);
        ls1 += __shfl_xor_sync(0xffffffffu, ls1, 2);
        l0s = l0s * al0 + ls0;
        l1s = l1s * al1 + ls1;
        m0s = mn0; m1s = mn1;

        #pragma unroll
        for (int nf = 0; nf < 8; nf++) {
            oacc[nf][0] *= al0; oacc[nf][1] *= al0;
            oacc[nf][2] *= al1; oacc[nf][3] *= al1;
        }

        const unsigned vhb = vb_u + buf * FK_B;
        #pragma unroll
        for (int ks = 0; ks < 4; ks++) {
            unsigned a0 = pa0[2 * ks],     a1 = pa1[2 * ks];
            unsigned a2 = pa0[2 * ks + 1], a3 = pa1[2 * ks + 1];
            #pragma unroll
            for (int no = 0; no < 4; no++) {
                unsigned addr = vhb +
                    ((ks * 16 + (lane & 15)) * QH + no * 16 + (lane >> 4) * 8) * 2;
                unsigned b0, b1, b2, b3;
                ldsm_x4_t(b0, b1, b2, b3, addr);
                mma_f16(oacc[no * 2],     a0, a1, a2, a3, b0, b1);
                mma_f16(oacc[no * 2 + 1], a0, a1, a2, a3, b2, b3);
            }
        }

        CP_WAIT0();
        __syncthreads();
    }

    const float i0 = 1.f / l0s;
    const float i1 = 1.f / l1s;
    const size_t row0 = qtok0 + m0 + (lane >> 2);
    #pragma unroll
    for (int no = 0; no < 8; no++) {
        const int cw = col0 + no * 8 + (lane & 3) * 2;
        *(__nv_bfloat162*)(O + row0 * D_MODEL + cw) =
            __floats2bfloat162_rn(oacc[no][0] * i0, oacc[no][1] * i0);
        *(__nv_bfloat162*)(O + (row0 + 8) * D_MODEL + cw) =
            __floats2bfloat162_rn(oacc[no][2] * i1, oacc[no][3] * i1);
    }
}

// ---------------- driver ----------------------------------------------------
extern "C" void kernel_launch(void* const* d_in, const int* in_sizes, int n_in,
                              void* d_out, int out_size)
{
    const float* x       = (const float*)d_in[0];
    const float* W_q     = (const float*)d_in[1];
    const float* W_k     = (const float*)d_in[2];
    const float* W_v     = (const float*)d_in[3];
    const float* W_o     = (const float*)d_in[4];
    const float* b_o     = (const float*)d_in[5];
    const float* a_nw    = (const float*)d_in[6];
    const float* f_nw    = (const float*)d_in[7];
    const float* W_gate  = (const float*)d_in[8];
    const float* W_hid   = (const float*)d_in[9];
    const float* W_out   = (const float*)d_in[10];
    const float* b_out   = (const float*)d_in[11];
    float* out = (float*)d_out;

    float *x1;
    __half *qh, *kh, *vh;
    __nv_bfloat16 *xnb, *atb, *hb, *wq, *wk, *wv, *wo, *wg, *wh, *wd;
    cudaGetSymbolAddress((void**)&qh,  g_qh);
    cudaGetSymbolAddress((void**)&kh,  g_kh);
    cudaGetSymbolAddress((void**)&vh,  g_vh);
    cudaGetSymbolAddress((void**)&x1,  g_x1);
    cudaGetSymbolAddress((void**)&xnb, g_xnb);
    cudaGetSymbolAddress((void**)&atb, g_atb);
    cudaGetSymbolAddress((void**)&hb,  g_hb);
    cudaGetSymbolAddress((void**)&wq,  g_wq);
    cudaGetSymbolAddress((void**)&wk,  g_wk);
    cudaGetSymbolAddress((void**)&wv,  g_wv);
    cudaGetSymbolAddress((void**)&wo,  g_wo);
    cudaGetSymbolAddress((void**)&wg,  g_wg);
    cudaGetSymbolAddress((void**)&wh,  g_wh);
    cudaGetSymbolAddress((void**)&wd,  g_wd);

    cudaFuncSetAttribute(flash4_kernel,
                         cudaFuncAttributeMaxDynamicSharedMemorySize, FL_SMEM);
    cudaFuncSetAttribute(mma_gemm_kernel<4>,
                         cudaFuncAttributeMaxDynamicSharedMemorySize, G5_SMEM_M128);
    cudaFuncSetAttribute(mma_gemm_kernel<2>,
                         cudaFuncAttributeMaxDynamicSharedMemorySize, G5_SMEM_M64);
    cudaFuncSetAttribute(mma_gemm_qkv,
                         cudaFuncAttributeMaxDynamicSharedMemorySize, G5_SMEM_M128);
    cudaFuncSetAttribute(swiglu_gemm_kernel,
                         cudaFuncAttributeMaxDynamicSharedMemorySize, SWI_SMEM);

    // 1) QKV/O weight cvt + attn rmsnorm, one launch
    prep_kernel<<<8192, 256>>>(x, a_nw, xnb, W_q, W_k, W_v, W_o,
                               wq, wk, wv, wo);

    // 2) q, k, v projections + FFN weight conversion plane (z==3 fills tail)
    dim3 gqkv(D_MODEL / 128, N_TOK / 128, 4);
    mma_gemm_qkv<<<gqkv, 256, G5_SMEM_M128>>>(xnb, wq, wk, wv, qh, kh, vh,
                                              N_TOK, D_MODEL, D_MODEL,
                                              W_gate, W_hid, W_out, wg, wh, wd);

    // 3) attention -> bf16
    dim3 ga(SEQ / 128, N_HEADS, 2);
    flash4_kernel<<<ga, 256, FL_SMEM>>>(qh, kh, vh, atb);

    // 4) output projection + bias + residual (M=64 tiles: full chip)
    dim3 go(D_MODEL / 128, N_TOK / 64);
    mma_gemm_kernel<2><<<go, 256, G5_SMEM_M64>>>(atb, wo, b_o, x, x1,
                                                 N_TOK, D_MODEL, D_MODEL);

    // 5) ffn rmsnorm -> bf16
    rmsnorm_kernel<<<N_TOK, 256>>>(x1, f_nw, xnb);

    // 6+7) fused gate/hidden GEMMs + SwiGLU -> hb bf16
    dim3 gf(D_FF / 128, N_TOK / 128);
    swiglu_gemm_kernel<<<gf, 256, SWI_SMEM>>>(xnb, wg, wh, hb,
                                              N_TOK, D_FF, D_MODEL);

    // 8) down projection + bias + residual -> out
    dim3 gd(D_MODEL / 128, N_TOK / 128);
    mma_gemm_kernel<4><<<gd, 256, G5_SMEM_M128>>>(hb, wd, b_out, x1, out,
                                                  N_TOK, D_MODEL, D_FF);
}